// round 6
// baseline (speedup 1.0000x reference)
#include <cuda_runtime.h>
#include <cuda_bf16.h>
#include <cstdint>

// Problem constants
#define BB 16
#define CC 64
#define HH 256
#define WW 256
#define GG 8
#define GS 8

// ---------------- k1 tiling ----------------
// CTA tile: M=256 pixels (2 rows x 128 cols) x N=64 couts, K = 9 taps x 64 cin.
// A smem: 4 image rows x 130 halo pixels, each pixel-row = 64 ci bf16 = 128B (swizzled).
// B smem: 2 terms x 9 taps x [64 co][64 ci] bf16 (swizzled), staged once.
// Epilogue reuses the A region as a fp32 [256][68] transpose buffer.
#define EPI_PAD 68
#define EPI_BYTES (256 * EPI_PAD * 4)      // 69632 (>= A raw 66560)
#define B_OFF EPI_BYTES
#define B_TERM_BYTES 73728                  // 9*64*64*2
#define B_BYTES (2 * B_TERM_BYTES)          // 147456
#define SMEM1 (B_OFF + B_BYTES)             // 217088

// Big device buffers (bss, not allocations)
__device__ float g_xconv[(size_t)BB * HH * WW * CC];           // [b][h][w][c]
__device__ __align__(16) __nv_bfloat16 g_wsw[2][9][CC * CC];   // [term][tap][co][ci] swizzled

__device__ __forceinline__ uint32_t smem_u32(const void* p) {
    uint32_t a;
    asm("{ .reg .u64 t; cvta.to.shared.u64 t, %1; cvt.u32.u64 %0, t; }" : "=r"(a) : "l"(p));
    return a;
}
__device__ __forceinline__ void ldsm4(uint32_t* r, uint32_t addr) {
    asm volatile("ldmatrix.sync.aligned.m8n8.x4.shared.b16 {%0,%1,%2,%3}, [%4];"
                 : "=r"(r[0]), "=r"(r[1]), "=r"(r[2]), "=r"(r[3]) : "r"(addr));
}
__device__ __forceinline__ void hmma(float* c, const uint32_t* a, const uint32_t* b) {
    asm volatile(
        "mma.sync.aligned.m16n8k16.row.col.f32.bf16.bf16.f32 "
        "{%0,%1,%2,%3}, {%4,%5,%6,%7}, {%8,%9}, {%0,%1,%2,%3};"
        : "+f"(c[0]), "+f"(c[1]), "+f"(c[2]), "+f"(c[3])
        : "r"(a[0]), "r"(a[1]), "r"(a[2]), "r"(a[3]), "r"(b[0]), "r"(b[1]));
}

// ---------------------------------------------------------------------------
// k0w: weights -> bf16 hi/lo, layout [term][tap][co][ci] with 16B-chunk swizzle
// ---------------------------------------------------------------------------
extern "C" __global__ void k0_wconv(const float* __restrict__ w)
{
    int tap = blockIdx.x;     // 0..8
    int term = blockIdx.y;    // 0 hi, 1 lo
    for (int i = threadIdx.x; i < CC * CC; i += 256) {
        int co = i >> 6, ci = i & 63;
        float v = w[(size_t)(co * CC + ci) * 9 + tap];
        __nv_bfloat16 hi = __float2bfloat16(v);
        __nv_bfloat16 o = (term == 0) ? hi : __float2bfloat16(v - __bfloat162float(hi));
        uint32_t byte = (uint32_t)co * 128 + ((((uint32_t)ci >> 3) ^ ((uint32_t)co & 7)) << 4)
                      + ((uint32_t)ci & 7) * 2;
        g_wsw[term][tap][byte >> 1] = o;
    }
}

// ---------------------------------------------------------------------------
// k1: conv3x3 + bias via mma.sync bf16 (3-term split), out [b][h][w][c]
//   A staged directly from fp32 x (NCHW) with inline hi/lo bf16 conversion.
//   grid (2, 128, 16) = (w-half, h-pair, b); 256 threads (8 warps)
// ---------------------------------------------------------------------------
extern "C" __global__ void __launch_bounds__(256, 1)
k1_conv(const float* __restrict__ x,
        const float* __restrict__ cb)
{
    extern __shared__ char smem[];
    const uint32_t sA = smem_u32(smem);
    const uint32_t sB = sA + B_OFF;
    const int tid = threadIdx.x;
    const int wid = tid >> 5;
    const int lid = tid & 31;

    const int b  = blockIdx.z;
    const int h0 = blockIdx.y * 2;
    const int w0 = blockIdx.x * 128;

    // ---- stage B (both terms, once): 9216 uint4 from pre-swizzled g_wsw ----
    {
        const uint4* src = (const uint4*)&g_wsw[0][0][0];
        uint4* dst = (uint4*)(smem + B_OFF);
        for (int i = tid; i < B_BYTES / 16; i += 256) dst[i] = src[i];
    }

    // ldmatrix lane constants
    const int am  = lid & 15;            // A: pixel offset within m16
    const int akh = (lid >> 4) & 1;      // A: k-half (8 ci)
    const int bco = (lid & 7) + ((lid >= 16) ? 8 : 0);  // B: co within n16
    const int bkh = (lid >> 3) & 1;      // B: k-half
    const int pbase = wid * 16;

    const float* xb = x + (size_t)b * CC * HH * WW;

    float c[2][8][4];
#pragma unroll
    for (int hh = 0; hh < 2; hh++)
#pragma unroll
        for (int nb = 0; nb < 8; nb++)
#pragma unroll
            for (int q = 0; q < 4; q++) c[hh][nb][q] = 0.f;

    for (int aterm = 0; aterm < 2; aterm++) {      // 0 = x_hi, 1 = x_lo
        __syncthreads();   // B staged (first pass) / previous MMA phase done
        // ---- stage A: 4 image rows (h0-1..h0+2) x 130 halo px, fp32 -> bf16 ----
        // i -> (R, ci-pair, q); two coalesced channel rows per iteration,
        // packed into one u32 smem store (2 adjacent ci in same swizzle chunk).
        for (int i = tid; i < 4 * 32 * 130; i += 256) {
            int R  = i / (32 * 130);
            int r  = i - R * (32 * 130);
            int cp = r / 130;
            int q  = r - cp * 130;
            int gh = h0 - 1 + R;
            int gw = w0 - 1 + q;
            float v0 = 0.f, v1 = 0.f;
            if ((unsigned)gh < (unsigned)HH && (unsigned)gw < (unsigned)WW) {
                const float* p = xb + (size_t)(2 * cp) * HH * WW + (size_t)gh * WW + gw;
                v0 = p[0];
                v1 = p[HH * WW];
            }
            __nv_bfloat16 b0 = __float2bfloat16(v0);
            __nv_bfloat16 b1 = __float2bfloat16(v1);
            if (aterm) {
                b0 = __float2bfloat16(v0 - __bfloat162float(b0));
                b1 = __float2bfloat16(v1 - __bfloat162float(b1));
            }
            uint32_t pack = (uint32_t)__bfloat16_as_ushort(b0)
                          | ((uint32_t)__bfloat16_as_ushort(b1) << 16);
            int rs  = R * 130 + q;
            int ci0 = cp * 2;
            uint32_t off = (uint32_t)rs * 128
                         + ((((uint32_t)ci0 >> 3) ^ ((uint32_t)rs & 7)) << 4)
                         + ((uint32_t)ci0 & 7) * 2;
            *(uint32_t*)(smem + off) = pack;
        }
        __syncthreads();

        const int nbt = 2 - aterm;   // xh pairs with {wh, wl}; xl with {wh}
        for (int tap = 0; tap < 9; tap++) {
            const int dy = tap / 3, dx = tap - 3 * (tap / 3);
            const uint32_t btap = sB + tap * 8192 + bco * 128;
#pragma unroll
            for (int kb = 0; kb < 4; kb++) {
                uint32_t a[2][4];
#pragma unroll
                for (int hh = 0; hh < 2; hh++) {
                    int rs = (hh + dy) * 130 + pbase + dx + am;
                    uint32_t addr = sA + rs * 128
                                  + ((((uint32_t)(kb * 2 + akh)) ^ (rs & 7)) << 4);
                    ldsm4(a[hh], addr);
                }
                for (int bt = 0; bt < nbt; bt++) {
                    uint32_t bb[4][4];
#pragma unroll
                    for (int j = 0; j < 4; j++) {
                        uint32_t co = (uint32_t)(j * 16 + bco);
                        uint32_t addr = btap + bt * B_TERM_BYTES + j * 16 * 128
                                      + ((((uint32_t)(kb * 2 + bkh)) ^ (co & 7)) << 4);
                        ldsm4(bb[j], addr);
                    }
#pragma unroll
                    for (int hh = 0; hh < 2; hh++)
#pragma unroll
                        for (int j = 0; j < 4; j++) {
                            hmma(c[hh][2 * j + 0], a[hh], &bb[j][0]);
                            hmma(c[hh][2 * j + 1], a[hh], &bb[j][2]);
                        }
                }
            }
        }
    }

    // ---- epilogue: C frags -> smem [256 px][68] f32 -> coalesced gmem ----
    __syncthreads();
    float* smf = (float*)smem;
    const int mrow = (lid >> 2);
    const int qcol = (lid & 3) * 2;
#pragma unroll
    for (int hh = 0; hh < 2; hh++)
#pragma unroll
        for (int nb = 0; nb < 8; nb++) {
            int m0 = hh * 128 + pbase + mrow;
            int co = nb * 8 + qcol;
            *(float2*)&smf[m0 * EPI_PAD + co]       = make_float2(c[hh][nb][0], c[hh][nb][1]);
            *(float2*)&smf[(m0 + 8) * EPI_PAD + co] = make_float2(c[hh][nb][2], c[hh][nb][3]);
        }
    __syncthreads();

    for (int i = tid; i < 256 * 16; i += 256) {
        int pix = i >> 4, k4 = i & 15;
        float4 v = *(float4*)&smf[pix * EPI_PAD + k4 * 4];
        int cc4 = k4 * 4;
        v.x += __ldg(cb + cc4 + 0);
        v.y += __ldg(cb + cc4 + 1);
        v.z += __ldg(cb + cc4 + 2);
        v.w += __ldg(cb + cc4 + 3);
        int gh = h0 + (pix >> 7);
        int gw = w0 + (pix & 127);
        *(float4*)(g_xconv + (((size_t)b * HH + gh) * WW + gw) * CC + cc4) = v;
    }
}

// ---------------------------------------------------------------------------
// k2: fused depthwise-diag conv + group stats + gate + residual + LSE
//   (reads x_conv in [b][h][w][c] layout -> coalesced staging; HW tanh)
// ---------------------------------------------------------------------------
#define TW 32
#define TH 8
#define HALO_W (TW + 2)
#define HALO_H (TH + 2)
#define XTILE (HALO_W * HALO_H)
#define XS_FLOATS (CC * XTILE)

extern "C" __global__ void __launch_bounds__(256, 2)
k2_fused(const float* __restrict__ w,
         const float* __restrict__ cb,
         const float* __restrict__ gscale,
         const float* __restrict__ gbias,
         float* __restrict__ out)
{
    extern __shared__ float smemf[];
    float* xs  = smemf;
    float* wd  = smemf + XS_FLOATS;
    float* cbs = wd + CC * 9;
    float* gss = cbs + CC;
    float* gbs = gss + CC;

    const int tid = threadIdx.x;
    const int b  = blockIdx.z;
    const int h0 = blockIdx.y * TH;
    const int w0 = blockIdx.x * TW;

    const float* xb = g_xconv + (size_t)b * HH * WW * CC;
    for (int i = tid; i < XTILE * CC; i += 256) {
        int pix = i >> 6;
        int ci  = i & 63;
        int row = pix / HALO_W;
        int col = pix - row * HALO_W;
        int gh = h0 + row - 1;
        int gw = w0 + col - 1;
        float v = 0.f;
        if ((unsigned)gh < (unsigned)HH && (unsigned)gw < (unsigned)WW)
            v = xb[((size_t)gh * WW + gw) * CC + ci];
        xs[ci * XTILE + pix] = v;
    }
    for (int i = tid; i < CC * 9; i += 256) {
        int cch = i / 9, tap = i - 9 * (i / 9);
        wd[i] = w[(size_t)cch * (CC * 9) + cch * 9 + tap];
    }
    if (tid < CC) {
        cbs[tid] = cb[tid];
        gss[tid] = gscale[tid];
        gbs[tid] = gbias[tid];
    }
    __syncthreads();

    const int lx = tid & 31;
    const int ly = tid >> 5;
    const int center = (ly + 1) * HALO_W + (lx + 1);

    float m = -1e30f;
#pragma unroll
    for (int cch = 0; cch < CC; cch++)
        m = fmaxf(m, xs[cch * XTILE + center]);
    m += 1.0f;

    float s = 0.f;
    for (int g = 0; g < GG; g++) {
        float xc[GS];
        float sum = 0.f;
#pragma unroll
        for (int j = 0; j < GS; j++) {
            xc[j] = xs[(g * GS + j) * XTILE + center];
            sum += xc[j];
        }
        float mean = sum * (1.0f / GS);
        float vs = 0.f;
#pragma unroll
        for (int j = 0; j < GS; j++) {
            float dd = xc[j] - mean;
            vs = fmaf(dd, dd, vs);
        }
        float inv = rsqrtf(vs * (1.0f / GS) + 1e-5f);

#pragma unroll
        for (int j = 0; j < GS; j++) {
            int cch = g * GS + j;
            const float* xcp = xs + cch * XTILE;
            const float* wdp = wd + cch * 9;
            float a = cbs[cch];
#pragma unroll
            for (int t = 0; t < 9; t++) {
                int dy = t / 3, dx = t - 3 * (t / 3);
                a = fmaf(wdp[t], xcp[(ly + dy) * HALO_W + (lx + dx)], a);
            }
            float norm = (a - mean) * inv * gss[cch] + gbs[cch];
            float gate = __saturatef(norm * (1.0f / 6.0f) + 0.5f);
            float th;
            asm("tanh.approx.f32 %0, %1;" : "=f"(th) : "f"(norm));
            float v = xc[j] + th * gate;
            s += __expf(v - m);
        }
    }

    out[((size_t)b << 16) + (h0 + ly) * WW + (w0 + lx)] = m + __logf(s);
}

// ---------------------------------------------------------------------------
extern "C" void kernel_launch(void* const* d_in, const int* in_sizes, int n_in,
                              void* d_out, int out_size)
{
    const float* x   = (const float*)d_in[0];
    const float* w   = (const float*)d_in[1];
    const float* cb  = (const float*)d_in[2];
    const float* gsc = (const float*)d_in[3];
    const float* gbi = (const float*)d_in[4];
    float* out = (float*)d_out;

    cudaFuncSetAttribute(k1_conv, cudaFuncAttributeMaxDynamicSharedMemorySize, SMEM1);
    const int smem2 = (XS_FLOATS + CC * 9 + 3 * CC) * sizeof(float);
    cudaFuncSetAttribute(k2_fused, cudaFuncAttributeMaxDynamicSharedMemorySize, smem2);

    k0_wconv<<<dim3(9, 2), 256>>>(w);

    dim3 grid1(2, 128, BB);
    k1_conv<<<grid1, 256, SMEM1>>>(x, cb);

    dim3 grid2(WW / TW, HH / TH, BB);
    k2_fused<<<grid2, 256, smem2>>>(w, cb, gsc, gbi, out);
}

// round 7
// speedup vs baseline: 1.4032x; 1.4032x over previous
#include <cuda_runtime.h>
#include <cuda_bf16.h>
#include <cstdint>

// Problem constants
#define BB 16
#define CC 64
#define HH 256
#define WW 256
#define GG 8
#define GS 8

// ---------------- k1 tiling ----------------
// CTA tile: M=128 pixels (1 row) x N=64 couts, K = 9 taps x 64 cin, bf16 split.
// A smem: 3 halo rows x 130 px x 128B (swizzled) = 49920 B
// B smem: double buffer, 1 tap-matrix [64 co][64 ci] bf16 = 8192 B each
#define A_ROWS (3 * 130)
#define A_BYTES (A_ROWS * 128)             // 49920
#define B_OFF A_BYTES
#define B_TAP 8192
#define SMEM1 (B_OFF + 2 * B_TAP)          // 66304
#define EPI_PAD 68
#define K0X_SMEM (256 * EPI_PAD * 4)       // 69632

// Big device buffers (bss, not allocations)
__device__ float g_xconv[(size_t)BB * HH * WW * CC];                     // [b][h][w][c]
__device__ __align__(16) __nv_bfloat16 g_xth[(size_t)BB * HH * WW * CC]; // x hi [b][h][w][c]
__device__ __align__(16) __nv_bfloat16 g_xtl[(size_t)BB * HH * WW * CC]; // x lo
__device__ __align__(16) __nv_bfloat16 g_wsw[2][9][CC * CC];             // [term][tap][co][ci] swizzled

__device__ __forceinline__ uint32_t smem_u32(const void* p) {
    uint32_t a;
    asm("{ .reg .u64 t; cvta.to.shared.u64 t, %1; cvt.u32.u64 %0, t; }" : "=r"(a) : "l"(p));
    return a;
}
__device__ __forceinline__ void ldsm4(uint32_t* r, uint32_t addr) {
    asm volatile("ldmatrix.sync.aligned.m8n8.x4.shared.b16 {%0,%1,%2,%3}, [%4];"
                 : "=r"(r[0]), "=r"(r[1]), "=r"(r[2]), "=r"(r[3]) : "r"(addr));
}
__device__ __forceinline__ void hmma(float* c, const uint32_t* a, const uint32_t* b) {
    asm volatile(
        "mma.sync.aligned.m16n8k16.row.col.f32.bf16.bf16.f32 "
        "{%0,%1,%2,%3}, {%4,%5,%6,%7}, {%8,%9}, {%0,%1,%2,%3};"
        : "+f"(c[0]), "+f"(c[1]), "+f"(c[2]), "+f"(c[3])
        : "r"(a[0]), "r"(a[1]), "r"(a[2]), "r"(a[3]), "r"(b[0]), "r"(b[1]));
}
__device__ __forceinline__ void cpa16(uint32_t dst, const void* src, int szbytes) {
    asm volatile("cp.async.ca.shared.global [%0], [%1], 16, %2;"
                 :: "r"(dst), "l"(src), "r"(szbytes) : "memory");
}
#define CPA_COMMIT() asm volatile("cp.async.commit_group;" ::: "memory")
#define CPA_WAIT0()  asm volatile("cp.async.wait_group 0;" ::: "memory")

// ---------------------------------------------------------------------------
// k0w: weights -> bf16 hi/lo, layout [term][tap][co][ci] with 16B-chunk swizzle
// ---------------------------------------------------------------------------
extern "C" __global__ void k0_wconv(const float* __restrict__ w)
{
    int tap = blockIdx.x;     // 0..8
    int term = blockIdx.y;    // 0 hi, 1 lo
    for (int i = threadIdx.x; i < CC * CC; i += 256) {
        int co = i >> 6, ci = i & 63;
        float v = w[(size_t)(co * CC + ci) * 9 + tap];
        __nv_bfloat16 hi = __float2bfloat16(v);
        __nv_bfloat16 o = (term == 0) ? hi : __float2bfloat16(v - __bfloat162float(hi));
        uint32_t byte = (uint32_t)co * 128 + ((((uint32_t)ci >> 3) ^ ((uint32_t)co & 7)) << 4)
                      + ((uint32_t)ci & 7) * 2;
        g_wsw[term][tap][byte >> 1] = o;
    }
}

// ---------------------------------------------------------------------------
// k0x: transpose x [b][c][h][w] f32 -> [b][h][w][c] bf16 hi and lo
// ---------------------------------------------------------------------------
extern "C" __global__ void __launch_bounds__(256, 1)
k0_xconv(const float* __restrict__ x)
{
    extern __shared__ uint32_t shp[];   // [256 pix][68] packed {hi, lo<<16}
    const int tid = threadIdx.x;
    const int b = blockIdx.x >> 8;
    const int h = blockIdx.x & 255;
    const float* xr = x + ((size_t)b * CC * HH + h) * WW;

    for (int c = 0; c < CC; c++) {
        float v = xr[(size_t)c * HH * WW + tid];
        __nv_bfloat16 hi = __float2bfloat16(v);
        __nv_bfloat16 lo = __float2bfloat16(v - __bfloat162float(hi));
        uint32_t p = (uint32_t)__bfloat16_as_ushort(hi)
                   | ((uint32_t)__bfloat16_as_ushort(lo) << 16);
        shp[tid * EPI_PAD + c] = p;
    }
    __syncthreads();

    __nv_bfloat16* oh = g_xth + (((size_t)b * HH + h) * WW) * CC;
    __nv_bfloat16* ol = g_xtl + (((size_t)b * HH + h) * WW) * CC;
    for (int i = tid; i < 256 * 16; i += 256) {
        int pix = i >> 4, k4 = i & 15;
        uint4 q = *(const uint4*)&shp[pix * EPI_PAD + k4 * 4];
        uint2 hv, lv;
        hv.x = (q.x & 0xFFFFu) | (q.y << 16);
        hv.y = (q.z & 0xFFFFu) | (q.w << 16);
        lv.x = (q.x >> 16) | (q.y & 0xFFFF0000u);
        lv.y = (q.z >> 16) | (q.w & 0xFFFF0000u);
        *(uint2*)(oh + (size_t)pix * CC + k4 * 4) = hv;
        *(uint2*)(ol + (size_t)pix * CC + k4 * 4) = lv;
    }
}

// ---------------------------------------------------------------------------
// k1: conv3x3 + bias via mma.sync bf16 (3-term split), out [b][h][w][c]
//   M=128, B streamed per-tap (cp.async double buffer), 27 tap-passes.
//   grid (2, 256, 16) = (w-half, h, b); 256 threads (8 warps)
// ---------------------------------------------------------------------------
extern "C" __global__ void __launch_bounds__(256, 2)
k1_conv(const float* __restrict__ cb)
{
    extern __shared__ char smem[];
    const uint32_t sA = smem_u32(smem);
    const int tid = threadIdx.x;
    const int wid = tid >> 5;
    const int lid = tid & 31;

    const int b  = blockIdx.z;
    const int h0 = blockIdx.y;
    const int w0 = blockIdx.x * 128;

    // ldmatrix lane constants
    const int am  = lid & 15;
    const int akh = (lid >> 4) & 1;
    const int bco = (lid & 7) + ((lid >= 16) ? 8 : 0);
    const int bkh = (lid >> 3) & 1;
    const int pbase = wid * 16;

    // ---- staging lambdas ----
    auto stageA = [&](const __nv_bfloat16* xt) {
        for (int i = tid; i < A_ROWS * 8; i += 256) {
            int rs = i >> 3, chunk = i & 7;
            int R  = rs / 130;
            int px = rs - R * 130;
            int gh = h0 - 1 + R;
            int gw = w0 - 1 + px;
            bool ok = ((unsigned)gh < (unsigned)HH) && ((unsigned)gw < (unsigned)WW);
            const __nv_bfloat16* src = xt + ((((size_t)b * HH + gh) * WW + gw) * CC) + chunk * 8;
            uint32_t dst = sA + rs * 128 + ((chunk ^ (rs & 7)) << 4);
            cpa16(dst, src, ok ? 16 : 0);
        }
    };
    auto stageB = [&](int buf, int bt, int tap) {
        const char* src = (const char*)&g_wsw[bt][tap][0];
        uint32_t dst = sA + B_OFF + buf * B_TAP;
        for (int i = tid; i < B_TAP / 16; i += 256)
            cpa16(dst + i * 16, src + i * 16, 16);
    };

    float c[8][4];
#pragma unroll
    for (int nb = 0; nb < 8; nb++)
#pragma unroll
        for (int q = 0; q < 4; q++) c[nb][q] = 0.f;

    // prologue: A(hi) + B(wh, tap0)
    stageA(g_xth);
    stageB(0, 0, 0);
    CPA_COMMIT();

    int cur = 0;
    for (int pass = 0; pass < 27; pass++) {
        CPA_WAIT0();
        __syncthreads();

        // prefetch next B
        if (pass < 26) {
            int np = pass + 1;
            int nbt = (np >= 9 && np < 18) ? 1 : 0;
            int ntap = (np < 9) ? np : (np < 18 ? np - 9 : np - 18);
            stageB(cur ^ 1, nbt, ntap);
            CPA_COMMIT();
        }

        const int tap = (pass < 9) ? pass : (pass < 18 ? pass - 9 : pass - 18);
        const int dy = tap / 3, dx = tap - 3 * (tap / 3);
        const uint32_t sBc = sA + B_OFF + cur * B_TAP;

#pragma unroll
        for (int kb = 0; kb < 4; kb++) {
            uint32_t a[4];
            {
                int rs = dy * 130 + pbase + dx + am;
                uint32_t addr = sA + rs * 128
                              + ((((uint32_t)(kb * 2 + akh)) ^ (rs & 7)) << 4);
                ldsm4(a, addr);
            }
            uint32_t bbf[4][4];
#pragma unroll
            for (int j = 0; j < 4; j++) {
                uint32_t co = (uint32_t)(j * 16 + bco);
                uint32_t addr = sBc + co * 128
                              + ((((uint32_t)(kb * 2 + bkh)) ^ (co & 7)) << 4);
                ldsm4(bbf[j], addr);
            }
#pragma unroll
            for (int j = 0; j < 4; j++) {
                hmma(c[2 * j + 0], a, &bbf[j][0]);
                hmma(c[2 * j + 1], a, &bbf[j][2]);
            }
        }

        // after last xh pass, restage A with xl
        if (pass == 17) {
            __syncthreads();
            stageA(g_xtl);
            CPA_COMMIT();
        }
        cur ^= 1;
    }

    // ---- epilogue: C frags -> smem [128 px][68] f32 -> coalesced gmem ----
    __syncthreads();
    float* smf = (float*)smem;
    const int mrow = (lid >> 2);
    const int qcol = (lid & 3) * 2;
#pragma unroll
    for (int nb = 0; nb < 8; nb++) {
        int m0 = pbase + mrow;
        int co = nb * 8 + qcol;
        *(float2*)&smf[m0 * EPI_PAD + co]       = make_float2(c[nb][0], c[nb][1]);
        *(float2*)&smf[(m0 + 8) * EPI_PAD + co] = make_float2(c[nb][2], c[nb][3]);
    }
    __syncthreads();

    for (int i = tid; i < 128 * 16; i += 256) {
        int pix = i >> 4, k4 = i & 15;
        float4 v = *(float4*)&smf[pix * EPI_PAD + k4 * 4];
        int cc4 = k4 * 4;
        v.x += __ldg(cb + cc4 + 0);
        v.y += __ldg(cb + cc4 + 1);
        v.z += __ldg(cb + cc4 + 2);
        v.w += __ldg(cb + cc4 + 3);
        *(float4*)(g_xconv + (((size_t)b * HH + h0) * WW + (w0 + pix)) * CC + cc4) = v;
    }
}

// ---------------------------------------------------------------------------
// k2: fused depthwise-diag conv + group stats + gate + residual + LSE
// ---------------------------------------------------------------------------
#define TW 32
#define TH 8
#define HALO_W (TW + 2)
#define HALO_H (TH + 2)
#define XTILE (HALO_W * HALO_H)
#define XS_FLOATS (CC * XTILE)

extern "C" __global__ void __launch_bounds__(256, 2)
k2_fused(const float* __restrict__ w,
         const float* __restrict__ cb,
         const float* __restrict__ gscale,
         const float* __restrict__ gbias,
         float* __restrict__ out)
{
    extern __shared__ float smemf[];
    float* xs  = smemf;
    float* wd  = smemf + XS_FLOATS;
    float* cbs = wd + CC * 9;
    float* gss = cbs + CC;
    float* gbs = gss + CC;

    const int tid = threadIdx.x;
    const int b  = blockIdx.z;
    const int h0 = blockIdx.y * TH;
    const int w0 = blockIdx.x * TW;

    const float* xb = g_xconv + (size_t)b * HH * WW * CC;
    for (int i = tid; i < XTILE * CC; i += 256) {
        int pix = i >> 6;
        int ci  = i & 63;
        int row = pix / HALO_W;
        int col = pix - row * HALO_W;
        int gh = h0 + row - 1;
        int gw = w0 + col - 1;
        float v = 0.f;
        if ((unsigned)gh < (unsigned)HH && (unsigned)gw < (unsigned)WW)
            v = xb[((size_t)gh * WW + gw) * CC + ci];
        xs[ci * XTILE + pix] = v;
    }
    for (int i = tid; i < CC * 9; i += 256) {
        int cch = i / 9, tap = i - 9 * (i / 9);
        wd[i] = w[(size_t)cch * (CC * 9) + cch * 9 + tap];
    }
    if (tid < CC) {
        cbs[tid] = cb[tid];
        gss[tid] = gscale[tid];
        gbs[tid] = gbias[tid];
    }
    __syncthreads();

    const int lx = tid & 31;
    const int ly = tid >> 5;
    const int center = (ly + 1) * HALO_W + (lx + 1);

    float m = -1e30f;
#pragma unroll
    for (int cch = 0; cch < CC; cch++)
        m = fmaxf(m, xs[cch * XTILE + center]);
    m += 1.0f;

    float s = 0.f;
    for (int g = 0; g < GG; g++) {
        float xc[GS];
        float sum = 0.f;
#pragma unroll
        for (int j = 0; j < GS; j++) {
            xc[j] = xs[(g * GS + j) * XTILE + center];
            sum += xc[j];
        }
        float mean = sum * (1.0f / GS);
        float vs = 0.f;
#pragma unroll
        for (int j = 0; j < GS; j++) {
            float dd = xc[j] - mean;
            vs = fmaf(dd, dd, vs);
        }
        float inv = rsqrtf(vs * (1.0f / GS) + 1e-5f);

#pragma unroll
        for (int j = 0; j < GS; j++) {
            int cch = g * GS + j;
            const float* xcp = xs + cch * XTILE;
            const float* wdp = wd + cch * 9;
            float a = cbs[cch];
#pragma unroll
            for (int t = 0; t < 9; t++) {
                int dy = t / 3, dx = t - 3 * (t / 3);
                a = fmaf(wdp[t], xcp[(ly + dy) * HALO_W + (lx + dx)], a);
            }
            float norm = (a - mean) * inv * gss[cch] + gbs[cch];
            float gate = __saturatef(norm * (1.0f / 6.0f) + 0.5f);
            float th;
            asm("tanh.approx.f32 %0, %1;" : "=f"(th) : "f"(norm));
            float v = xc[j] + th * gate;
            s += __expf(v - m);
        }
    }

    out[((size_t)b << 16) + (h0 + ly) * WW + (w0 + lx)] = m + __logf(s);
}

// ---------------------------------------------------------------------------
extern "C" void kernel_launch(void* const* d_in, const int* in_sizes, int n_in,
                              void* d_out, int out_size)
{
    const float* x   = (const float*)d_in[0];
    const float* w   = (const float*)d_in[1];
    const float* cb  = (const float*)d_in[2];
    const float* gsc = (const float*)d_in[3];
    const float* gbi = (const float*)d_in[4];
    float* out = (float*)d_out;

    cudaFuncSetAttribute(k0_xconv, cudaFuncAttributeMaxDynamicSharedMemorySize, K0X_SMEM);
    cudaFuncSetAttribute(k1_conv,  cudaFuncAttributeMaxDynamicSharedMemorySize, SMEM1);
    const int smem2 = (XS_FLOATS + CC * 9 + 3 * CC) * sizeof(float);
    cudaFuncSetAttribute(k2_fused, cudaFuncAttributeMaxDynamicSharedMemorySize, smem2);

    k0_wconv<<<dim3(9, 2), 256>>>(w);
    k0_xconv<<<BB * HH, 256, K0X_SMEM>>>(x);

    dim3 grid1(2, HH, BB);
    k1_conv<<<grid1, 256, SMEM1>>>(cb);

    dim3 grid2(WW / TW, HH / TH, BB);
    k2_fused<<<grid2, 256, smem2>>>(w, cb, gsc, gbi, out);
}

// round 8
// speedup vs baseline: 1.7842x; 1.2715x over previous
#include <cuda_runtime.h>
#include <cuda_bf16.h>
#include <cstdint>

// Problem constants
#define BB 16
#define CC 64
#define HH 256
#define WW 256
#define GG 8
#define GS 8

// ---------------- k1 tiling ----------------
// CTA tile: M=256 pixels (2 rows x 128 cols) x N=64 couts, K = 9 taps x 64 cin.
// A smem: 4 halo rows x 130 px x 128B (swizzled) = 66560 B (single buffer, restaged hi->lo)
// B smem: double buffer of tap-pair {wh, wl} = 2 x 16384 B, streamed per tap
#define A_ROWS (4 * 130)
#define A_BYTES (A_ROWS * 128)             // 66560
#define B_OFF A_BYTES
#define B_TAP 8192
#define B_BUF (2 * B_TAP)                  // 16384 {wh, wl}
#define SMEM1 (B_OFF + 2 * B_BUF)          // 99328
#define EPI_PAD 68
#define K0X_SMEM (256 * EPI_PAD * 4)       // 69632

// Big device buffers (bss, not allocations)
__device__ float g_xconv[(size_t)BB * HH * WW * CC];                     // [b][h][w][c]
__device__ __align__(16) __nv_bfloat16 g_xth[(size_t)BB * HH * WW * CC]; // x hi [b][h][w][c]
__device__ __align__(16) __nv_bfloat16 g_xtl[(size_t)BB * HH * WW * CC]; // x lo
__device__ __align__(16) __nv_bfloat16 g_wsw[2][9][CC * CC];             // [term][tap][co][ci] swizzled

__device__ __forceinline__ uint32_t smem_u32(const void* p) {
    uint32_t a;
    asm("{ .reg .u64 t; cvta.to.shared.u64 t, %1; cvt.u32.u64 %0, t; }" : "=r"(a) : "l"(p));
    return a;
}
__device__ __forceinline__ void ldsm4(uint32_t* r, uint32_t addr) {
    asm volatile("ldmatrix.sync.aligned.m8n8.x4.shared.b16 {%0,%1,%2,%3}, [%4];"
                 : "=r"(r[0]), "=r"(r[1]), "=r"(r[2]), "=r"(r[3]) : "r"(addr));
}
__device__ __forceinline__ void hmma(float* c, const uint32_t* a, const uint32_t* b) {
    asm volatile(
        "mma.sync.aligned.m16n8k16.row.col.f32.bf16.bf16.f32 "
        "{%0,%1,%2,%3}, {%4,%5,%6,%7}, {%8,%9}, {%0,%1,%2,%3};"
        : "+f"(c[0]), "+f"(c[1]), "+f"(c[2]), "+f"(c[3])
        : "r"(a[0]), "r"(a[1]), "r"(a[2]), "r"(a[3]), "r"(b[0]), "r"(b[1]));
}
__device__ __forceinline__ void cpa16(uint32_t dst, const void* src, int szbytes) {
    asm volatile("cp.async.ca.shared.global [%0], [%1], 16, %2;"
                 :: "r"(dst), "l"(src), "r"(szbytes) : "memory");
}
#define CPA_COMMIT() asm volatile("cp.async.commit_group;" ::: "memory")
#define CPA_WAIT0()  asm volatile("cp.async.wait_group 0;" ::: "memory")

// ---------------------------------------------------------------------------
// k0w: weights -> bf16 hi/lo, layout [term][tap][co][ci] with 16B-chunk swizzle
// ---------------------------------------------------------------------------
extern "C" __global__ void k0_wconv(const float* __restrict__ w)
{
    int tap = blockIdx.x;     // 0..8
    int term = blockIdx.y;    // 0 hi, 1 lo
    for (int i = threadIdx.x; i < CC * CC; i += 256) {
        int co = i >> 6, ci = i & 63;
        float v = w[(size_t)(co * CC + ci) * 9 + tap];
        __nv_bfloat16 hi = __float2bfloat16(v);
        __nv_bfloat16 o = (term == 0) ? hi : __float2bfloat16(v - __bfloat162float(hi));
        uint32_t byte = (uint32_t)co * 128 + ((((uint32_t)ci >> 3) ^ ((uint32_t)co & 7)) << 4)
                      + ((uint32_t)ci & 7) * 2;
        g_wsw[term][tap][byte >> 1] = o;
    }
}

// ---------------------------------------------------------------------------
// k0x: transpose x [b][c][h][w] f32 -> [b][h][w][c] bf16 hi and lo
// ---------------------------------------------------------------------------
extern "C" __global__ void __launch_bounds__(256, 1)
k0_xconv(const float* __restrict__ x)
{
    extern __shared__ uint32_t shp[];   // [256 pix][68] packed {hi, lo<<16}
    const int tid = threadIdx.x;
    const int b = blockIdx.x >> 8;
    const int h = blockIdx.x & 255;
    const float* xr = x + ((size_t)b * CC * HH + h) * WW;

    for (int c = 0; c < CC; c++) {
        float v = xr[(size_t)c * HH * WW + tid];
        __nv_bfloat16 hi = __float2bfloat16(v);
        __nv_bfloat16 lo = __float2bfloat16(v - __bfloat162float(hi));
        uint32_t p = (uint32_t)__bfloat16_as_ushort(hi)
                   | ((uint32_t)__bfloat16_as_ushort(lo) << 16);
        shp[tid * EPI_PAD + c] = p;
    }
    __syncthreads();

    __nv_bfloat16* oh = g_xth + (((size_t)b * HH + h) * WW) * CC;
    __nv_bfloat16* ol = g_xtl + (((size_t)b * HH + h) * WW) * CC;
    for (int i = tid; i < 256 * 16; i += 256) {
        int pix = i >> 4, k4 = i & 15;
        uint4 q = *(const uint4*)&shp[pix * EPI_PAD + k4 * 4];
        uint2 hv, lv;
        hv.x = (q.x & 0xFFFFu) | (q.y << 16);
        hv.y = (q.z & 0xFFFFu) | (q.w << 16);
        lv.x = (q.x >> 16) | (q.y & 0xFFFF0000u);
        lv.y = (q.z >> 16) | (q.w & 0xFFFF0000u);
        *(uint2*)(oh + (size_t)pix * CC + k4 * 4) = hv;
        *(uint2*)(ol + (size_t)pix * CC + k4 * 4) = lv;
    }
}

// ---------------------------------------------------------------------------
// k1: conv3x3 + bias via mma.sync bf16 (3-term split), out [b][h][w][c]
//   M=256, B streamed per tap-pair {wh,wl} double-buffered. 18 tap-passes:
//   passes 0-8:  A=x_hi, MMA vs wh AND wl
//   passes 9-17: A=x_lo, MMA vs wh only
//   grid (2, 128, 16) = (w-half, h-pair, b); 256 threads (8 warps); 2 CTAs/SM
// ---------------------------------------------------------------------------
extern "C" __global__ void __launch_bounds__(256, 2)
k1_conv(const float* __restrict__ cb)
{
    extern __shared__ char smem[];
    const uint32_t sA = smem_u32(smem);
    const int tid = threadIdx.x;
    const int wid = tid >> 5;
    const int lid = tid & 31;

    const int b  = blockIdx.z;
    const int h0 = blockIdx.y * 2;
    const int w0 = blockIdx.x * 128;

    // ldmatrix lane constants
    const int am  = lid & 15;
    const int akh = (lid >> 4) & 1;
    const int bco = (lid & 7) + ((lid >= 16) ? 8 : 0);
    const int bkh = (lid >> 3) & 1;
    const int pbase = wid * 16;

    auto stageA = [&](const __nv_bfloat16* xt) {
        for (int i = tid; i < A_ROWS * 8; i += 256) {
            int rs = i >> 3, chunk = i & 7;
            int R  = rs / 130;
            int px = rs - R * 130;
            int gh = h0 - 1 + R;
            int gw = w0 - 1 + px;
            bool ok = ((unsigned)gh < (unsigned)HH) && ((unsigned)gw < (unsigned)WW);
            const __nv_bfloat16* src = xt + ((((size_t)b * HH + gh) * WW + gw) * CC) + chunk * 8;
            uint32_t dst = sA + rs * 128 + ((chunk ^ (rs & 7)) << 4);
            cpa16(dst, src, ok ? 16 : 0);
        }
    };
    // stage {wh[tap]} and optionally {wl[tap]} into buffer buf
    auto stageB = [&](int buf, int tap, int both) {
        uint32_t dst = sA + B_OFF + buf * B_BUF;
        const char* s0 = (const char*)&g_wsw[0][tap][0];
        for (int i = tid; i < B_TAP / 16; i += 256)
            cpa16(dst + i * 16, s0 + i * 16, 16);
        if (both) {
            const char* s1 = (const char*)&g_wsw[1][tap][0];
            for (int i = tid; i < B_TAP / 16; i += 256)
                cpa16(dst + B_TAP + i * 16, s1 + i * 16, 16);
        }
    };

    float c[2][8][4];
#pragma unroll
    for (int hh = 0; hh < 2; hh++)
#pragma unroll
        for (int nb = 0; nb < 8; nb++)
#pragma unroll
            for (int q = 0; q < 4; q++) c[hh][nb][q] = 0.f;

    // prologue
    stageA(g_xth);
    stageB(0, 0, 1);
    CPA_COMMIT();

    int cur = 0;
    for (int pass = 0; pass < 18; pass++) {
        CPA_WAIT0();
        __syncthreads();

        // prefetch next B (except when A must be restaged first, and at end)
        if (pass < 17 && pass != 8) {
            int np = pass + 1;
            int ntap = (np < 9) ? np : np - 9;
            stageB(cur ^ 1, ntap, np < 9);
            CPA_COMMIT();
        }

        const int tap = (pass < 9) ? pass : pass - 9;
        const int dy = tap / 3, dx = tap - 3 * (tap / 3);
        const int nbt = (pass < 9) ? 2 : 1;
        const uint32_t sBc = sA + B_OFF + cur * B_BUF + bco * 128;

#pragma unroll
        for (int kb = 0; kb < 4; kb++) {
            uint32_t a[2][4];
#pragma unroll
            for (int hh = 0; hh < 2; hh++) {
                int rs = (hh + dy) * 130 + pbase + dx + am;
                uint32_t addr = sA + rs * 128
                              + ((((uint32_t)(kb * 2 + akh)) ^ (rs & 7)) << 4);
                ldsm4(a[hh], addr);
            }
            for (int bt = 0; bt < nbt; bt++) {
                uint32_t bbf[4][4];
#pragma unroll
                for (int j = 0; j < 4; j++) {
                    uint32_t co = (uint32_t)(j * 16 + bco);
                    uint32_t addr = sBc + bt * B_TAP + j * 16 * 128
                                  + ((((uint32_t)(kb * 2 + bkh)) ^ (co & 7)) << 4);
                    ldsm4(bbf[j], addr);
                }
#pragma unroll
                for (int hh = 0; hh < 2; hh++)
#pragma unroll
                    for (int j = 0; j < 4; j++) {
                        hmma(c[hh][2 * j + 0], a[hh], &bbf[j][0]);
                        hmma(c[hh][2 * j + 1], a[hh], &bbf[j][2]);
                    }
            }
        }

        // after last x_hi pass: restage A with x_lo, plus B(tap0, wh) for pass 9
        if (pass == 8) {
            __syncthreads();       // all warps done with A reads
            stageA(g_xtl);
            stageB(cur ^ 1, 0, 0);
            CPA_COMMIT();
        }
        cur ^= 1;
    }

    // ---- epilogue: C frags -> smem [256 px][68] f32 -> coalesced gmem ----
    __syncthreads();
    float* smf = (float*)smem;
    const int mrow = (lid >> 2);
    const int qcol = (lid & 3) * 2;
#pragma unroll
    for (int hh = 0; hh < 2; hh++)
#pragma unroll
        for (int nb = 0; nb < 8; nb++) {
            int m0 = hh * 128 + pbase + mrow;
            int co = nb * 8 + qcol;
            *(float2*)&smf[m0 * EPI_PAD + co]       = make_float2(c[hh][nb][0], c[hh][nb][1]);
            *(float2*)&smf[(m0 + 8) * EPI_PAD + co] = make_float2(c[hh][nb][2], c[hh][nb][3]);
        }
    __syncthreads();

    for (int i = tid; i < 256 * 16; i += 256) {
        int pix = i >> 4, k4 = i & 15;
        float4 v = *(float4*)&smf[pix * EPI_PAD + k4 * 4];
        int cc4 = k4 * 4;
        v.x += __ldg(cb + cc4 + 0);
        v.y += __ldg(cb + cc4 + 1);
        v.z += __ldg(cb + cc4 + 2);
        v.w += __ldg(cb + cc4 + 3);
        int gh = h0 + (pix >> 7);
        int gw = w0 + (pix & 127);
        *(float4*)(g_xconv + (((size_t)b * HH + gh) * WW + gw) * CC + cc4) = v;
    }
}

// ---------------------------------------------------------------------------
// k2: fused depthwise-diag conv + group stats + gate + residual + LSE
//   XTILE padded to odd stride (341) -> conflict-free staging stores
// ---------------------------------------------------------------------------
#define TW 32
#define TH 8
#define HALO_W (TW + 2)
#define HALO_H (TH + 2)
#define XTILE_RAW (HALO_W * HALO_H)        // 340
#define XTILE 341                           // odd stride: no STS bank conflicts
#define XS_FLOATS (CC * XTILE)

extern "C" __global__ void __launch_bounds__(256, 2)
k2_fused(const float* __restrict__ w,
         const float* __restrict__ cb,
         const float* __restrict__ gscale,
         const float* __restrict__ gbias,
         float* __restrict__ out)
{
    extern __shared__ float smemf[];
    float* xs  = smemf;
    float* wd  = smemf + XS_FLOATS;
    float* cbs = wd + CC * 9;
    float* gss = cbs + CC;
    float* gbs = gss + CC;

    const int tid = threadIdx.x;
    const int b  = blockIdx.z;
    const int h0 = blockIdx.y * TH;
    const int w0 = blockIdx.x * TW;

    const float* xb = g_xconv + (size_t)b * HH * WW * CC;
    for (int i = tid; i < XTILE_RAW * CC; i += 256) {
        int pix = i >> 6;
        int ci  = i & 63;
        int row = pix / HALO_W;
        int col = pix - row * HALO_W;
        int gh = h0 + row - 1;
        int gw = w0 + col - 1;
        float v = 0.f;
        if ((unsigned)gh < (unsigned)HH && (unsigned)gw < (unsigned)WW)
            v = xb[((size_t)gh * WW + gw) * CC + ci];
        xs[ci * XTILE + pix] = v;
    }
    for (int i = tid; i < CC * 9; i += 256) {
        int cch = i / 9, tap = i - 9 * (i / 9);
        wd[i] = w[(size_t)cch * (CC * 9) + cch * 9 + tap];
    }
    if (tid < CC) {
        cbs[tid] = cb[tid];
        gss[tid] = gscale[tid];
        gbs[tid] = gbias[tid];
    }
    __syncthreads();

    const int lx = tid & 31;
    const int ly = tid >> 5;
    const int center = (ly + 1) * HALO_W + (lx + 1);

    float m = -1e30f;
#pragma unroll
    for (int cch = 0; cch < CC; cch++)
        m = fmaxf(m, xs[cch * XTILE + center]);
    m += 1.0f;

    float s = 0.f;
    for (int g = 0; g < GG; g++) {
        float xc[GS];
        float sum = 0.f;
#pragma unroll
        for (int j = 0; j < GS; j++) {
            xc[j] = xs[(g * GS + j) * XTILE + center];
            sum += xc[j];
        }
        float mean = sum * (1.0f / GS);
        float vs = 0.f;
#pragma unroll
        for (int j = 0; j < GS; j++) {
            float dd = xc[j] - mean;
            vs = fmaf(dd, dd, vs);
        }
        float inv = rsqrtf(vs * (1.0f / GS) + 1e-5f);

#pragma unroll
        for (int j = 0; j < GS; j++) {
            int cch = g * GS + j;
            const float* xcp = xs + cch * XTILE;
            const float* wdp = wd + cch * 9;
            float a = cbs[cch];
#pragma unroll
            for (int t = 0; t < 9; t++) {
                int dy = t / 3, dx = t - 3 * (t / 3);
                a = fmaf(wdp[t], xcp[(ly + dy) * HALO_W + (lx + dx)], a);
            }
            float norm = (a - mean) * inv * gss[cch] + gbs[cch];
            float gate = __saturatef(norm * (1.0f / 6.0f) + 0.5f);
            float th;
            asm("tanh.approx.f32 %0, %1;" : "=f"(th) : "f"(norm));
            float v = xc[j] + th * gate;
            s += __expf(v - m);
        }
    }

    out[((size_t)b << 16) + (h0 + ly) * WW + (w0 + lx)] = m + __logf(s);
}

// ---------------------------------------------------------------------------
extern "C" void kernel_launch(void* const* d_in, const int* in_sizes, int n_in,
                              void* d_out, int out_size)
{
    const float* x   = (const float*)d_in[0];
    const float* w   = (const float*)d_in[1];
    const float* cb  = (const float*)d_in[2];
    const float* gsc = (const float*)d_in[3];
    const float* gbi = (const float*)d_in[4];
    float* out = (float*)d_out;

    cudaFuncSetAttribute(k0_xconv, cudaFuncAttributeMaxDynamicSharedMemorySize, K0X_SMEM);
    cudaFuncSetAttribute(k1_conv,  cudaFuncAttributeMaxDynamicSharedMemorySize, SMEM1);
    const int smem2 = (XS_FLOATS + CC * 9 + 3 * CC) * sizeof(float);
    cudaFuncSetAttribute(k2_fused, cudaFuncAttributeMaxDynamicSharedMemorySize, smem2);

    k0_wconv<<<dim3(9, 2), 256>>>(w);
    k0_xconv<<<BB * HH, 256, K0X_SMEM>>>(x);

    dim3 grid1(2, 128, BB);
    k1_conv<<<grid1, 256, SMEM1>>>(cb);

    dim3 grid2(WW / TW, HH / TH, BB);
    k2_fused<<<grid2, 256, smem2>>>(w, cb, gsc, gbi, out);
}

// round 11
// speedup vs baseline: 1.9902x; 1.1155x over previous
#include <cuda_runtime.h>
#include <cuda_bf16.h>
#include <cstdint>

// Problem constants
#define BB 16
#define CC 64
#define HH 256
#define WW 256
#define GG 8
#define GS 8

// ---------------- k1 tiling ----------------
#define A_ROWS (4 * 130)
#define A_BYTES (A_ROWS * 128)             // 66560
#define B_OFF A_BYTES
#define B_TAP 8192
#define B_BUF (2 * B_TAP)                  // 16384 {wh, wl}
#define SMEM1 (B_OFF + 2 * B_BUF)          // 99328
#define EPI_PAD 68
#define K0X_SMEM (256 * EPI_PAD * 4)       // 69632

// Big device buffers (bss, not allocations)
__device__ float g_xconv[(size_t)BB * HH * WW * CC];                     // [b][h][w][c]
__device__ __align__(16) __nv_bfloat16 g_xth[(size_t)BB * HH * WW * CC]; // x hi [b][h][w][c]
__device__ __align__(16) __nv_bfloat16 g_xtl[(size_t)BB * HH * WW * CC]; // x lo
__device__ __align__(16) __nv_bfloat16 g_wsw[2][9][CC * CC];             // [term][tap][co][ci] swizzled

__device__ __forceinline__ uint32_t smem_u32(const void* p) {
    uint32_t a;
    asm("{ .reg .u64 t; cvta.to.shared.u64 t, %1; cvt.u32.u64 %0, t; }" : "=r"(a) : "l"(p));
    return a;
}
__device__ __forceinline__ void ldsm4(uint32_t* r, uint32_t addr) {
    asm volatile("ldmatrix.sync.aligned.m8n8.x4.shared.b16 {%0,%1,%2,%3}, [%4];"
                 : "=r"(r[0]), "=r"(r[1]), "=r"(r[2]), "=r"(r[3]) : "r"(addr));
}
__device__ __forceinline__ void hmma(float* c, const uint32_t* a, const uint32_t* b) {
    asm volatile(
        "mma.sync.aligned.m16n8k16.row.col.f32.bf16.bf16.f32 "
        "{%0,%1,%2,%3}, {%4,%5,%6,%7}, {%8,%9}, {%0,%1,%2,%3};"
        : "+f"(c[0]), "+f"(c[1]), "+f"(c[2]), "+f"(c[3])
        : "r"(a[0]), "r"(a[1]), "r"(a[2]), "r"(a[3]), "r"(b[0]), "r"(b[1]));
}
__device__ __forceinline__ void cpa16(uint32_t dst, const void* src, int szbytes) {
    asm volatile("cp.async.ca.shared.global [%0], [%1], 16, %2;"
                 :: "r"(dst), "l"(src), "r"(szbytes) : "memory");
}
#define CPA_COMMIT() asm volatile("cp.async.commit_group;" ::: "memory")
#define CPA_WAIT0()  asm volatile("cp.async.wait_group 0;" ::: "memory")

// ---------------------------------------------------------------------------
// k0w: weights -> bf16 hi/lo, layout [term][tap][co][ci] with 16B-chunk swizzle
// ---------------------------------------------------------------------------
extern "C" __global__ void k0_wconv(const float* __restrict__ w)
{
    int tap = blockIdx.x;
    int term = blockIdx.y;
    for (int i = threadIdx.x; i < CC * CC; i += 256) {
        int co = i >> 6, ci = i & 63;
        float v = w[(size_t)(co * CC + ci) * 9 + tap];
        __nv_bfloat16 hi = __float2bfloat16(v);
        __nv_bfloat16 o = (term == 0) ? hi : __float2bfloat16(v - __bfloat162float(hi));
        uint32_t byte = (uint32_t)co * 128 + ((((uint32_t)ci >> 3) ^ ((uint32_t)co & 7)) << 4)
                      + ((uint32_t)ci & 7) * 2;
        g_wsw[term][tap][byte >> 1] = o;
    }
}

// ---------------------------------------------------------------------------
// k0x: transpose x [b][c][h][w] f32 -> [b][h][w][c] bf16 hi and lo
// ---------------------------------------------------------------------------
extern "C" __global__ void __launch_bounds__(256, 1)
k0_xconv(const float* __restrict__ x)
{
    extern __shared__ uint32_t shp[];   // [256 pix][68] packed {hi, lo<<16}
    const int tid = threadIdx.x;
    const int b = blockIdx.x >> 8;
    const int h = blockIdx.x & 255;
    const float* xr = x + ((size_t)b * CC * HH + h) * WW;

    for (int c = 0; c < CC; c++) {
        float v = xr[(size_t)c * HH * WW + tid];
        __nv_bfloat16 hi = __float2bfloat16(v);
        __nv_bfloat16 lo = __float2bfloat16(v - __bfloat162float(hi));
        uint32_t p = (uint32_t)__bfloat16_as_ushort(hi)
                   | ((uint32_t)__bfloat16_as_ushort(lo) << 16);
        shp[tid * EPI_PAD + c] = p;
    }
    __syncthreads();

    __nv_bfloat16* oh = g_xth + (((size_t)b * HH + h) * WW) * CC;
    __nv_bfloat16* ol = g_xtl + (((size_t)b * HH + h) * WW) * CC;
    for (int i = tid; i < 256 * 16; i += 256) {
        int pix = i >> 4, k4 = i & 15;
        uint4 q = *(const uint4*)&shp[pix * EPI_PAD + k4 * 4];
        uint2 hv, lv;
        hv.x = (q.x & 0xFFFFu) | (q.y << 16);
        hv.y = (q.z & 0xFFFFu) | (q.w << 16);
        lv.x = (q.x >> 16) | (q.y & 0xFFFF0000u);
        lv.y = (q.z >> 16) | (q.w & 0xFFFF0000u);
        *(uint2*)(oh + (size_t)pix * CC + k4 * 4) = hv;
        *(uint2*)(ol + (size_t)pix * CC + k4 * 4) = lv;
    }
}

// ---------------------------------------------------------------------------
// k1: conv3x3 + bias via mma.sync bf16 (3-term split), out [b][h][w][c]
//   M=256, B streamed per tap-pair {wh,wl} double-buffered. 18 tap-passes.
// ---------------------------------------------------------------------------
extern "C" __global__ void __launch_bounds__(256, 2)
k1_conv(const float* __restrict__ cb)
{
    extern __shared__ char smem[];
    const uint32_t sA = smem_u32(smem);
    const int tid = threadIdx.x;
    const int wid = tid >> 5;
    const int lid = tid & 31;

    const int b  = blockIdx.z;
    const int h0 = blockIdx.y * 2;
    const int w0 = blockIdx.x * 128;

    const int am  = lid & 15;
    const int akh = (lid >> 4) & 1;
    const int bco = (lid & 7) + ((lid >= 16) ? 8 : 0);
    const int bkh = (lid >> 3) & 1;
    const int pbase = wid * 16;

    auto stageA = [&](const __nv_bfloat16* xt) {
        for (int i = tid; i < A_ROWS * 8; i += 256) {
            int rs = i >> 3, chunk = i & 7;
            int R  = rs / 130;
            int px = rs - R * 130;
            int gh = h0 - 1 + R;
            int gw = w0 - 1 + px;
            bool ok = ((unsigned)gh < (unsigned)HH) && ((unsigned)gw < (unsigned)WW);
            const __nv_bfloat16* src = xt + ((((size_t)b * HH + gh) * WW + gw) * CC) + chunk * 8;
            uint32_t dst = sA + rs * 128 + ((chunk ^ (rs & 7)) << 4);
            cpa16(dst, src, ok ? 16 : 0);
        }
    };
    auto stageB = [&](int buf, int tap, int both) {
        uint32_t dst = sA + B_OFF + buf * B_BUF;
        const char* s0 = (const char*)&g_wsw[0][tap][0];
        for (int i = tid; i < B_TAP / 16; i += 256)
            cpa16(dst + i * 16, s0 + i * 16, 16);
        if (both) {
            const char* s1 = (const char*)&g_wsw[1][tap][0];
            for (int i = tid; i < B_TAP / 16; i += 256)
                cpa16(dst + B_TAP + i * 16, s1 + i * 16, 16);
        }
    };

    float c[2][8][4];
#pragma unroll
    for (int hh = 0; hh < 2; hh++)
#pragma unroll
        for (int nb = 0; nb < 8; nb++)
#pragma unroll
            for (int q = 0; q < 4; q++) c[hh][nb][q] = 0.f;

    stageA(g_xth);
    stageB(0, 0, 1);
    CPA_COMMIT();

    int cur = 0;
    for (int pass = 0; pass < 18; pass++) {
        CPA_WAIT0();
        __syncthreads();

        if (pass < 17 && pass != 8) {
            int np = pass + 1;
            int ntap = (np < 9) ? np : np - 9;
            stageB(cur ^ 1, ntap, np < 9);
            CPA_COMMIT();
        }

        const int tap = (pass < 9) ? pass : pass - 9;
        const int dy = tap / 3, dx = tap - 3 * (tap / 3);
        const int nbt = (pass < 9) ? 2 : 1;
        const uint32_t sBc = sA + B_OFF + cur * B_BUF + bco * 128;

#pragma unroll
        for (int kb = 0; kb < 4; kb++) {
            uint32_t a[2][4];
#pragma unroll
            for (int hh = 0; hh < 2; hh++) {
                int rs = (hh + dy) * 130 + pbase + dx + am;
                uint32_t addr = sA + rs * 128
                              + ((((uint32_t)(kb * 2 + akh)) ^ (rs & 7)) << 4);
                ldsm4(a[hh], addr);
            }
            for (int bt = 0; bt < nbt; bt++) {
                uint32_t bbf[4][4];
#pragma unroll
                for (int j = 0; j < 4; j++) {
                    uint32_t co = (uint32_t)(j * 16 + bco);
                    uint32_t addr = sBc + bt * B_TAP + j * 16 * 128
                                  + ((((uint32_t)(kb * 2 + bkh)) ^ (co & 7)) << 4);
                    ldsm4(bbf[j], addr);
                }
#pragma unroll
                for (int hh = 0; hh < 2; hh++)
#pragma unroll
                    for (int j = 0; j < 4; j++) {
                        hmma(c[hh][2 * j + 0], a[hh], &bbf[j][0]);
                        hmma(c[hh][2 * j + 1], a[hh], &bbf[j][2]);
                    }
            }
        }

        if (pass == 8) {
            __syncthreads();
            stageA(g_xtl);
            stageB(cur ^ 1, 0, 0);
            CPA_COMMIT();
        }
        cur ^= 1;
    }

    // ---- epilogue ----
    __syncthreads();
    float* smf = (float*)smem;
    const int mrow = (lid >> 2);
    const int qcol = (lid & 3) * 2;
#pragma unroll
    for (int hh = 0; hh < 2; hh++)
#pragma unroll
        for (int nb = 0; nb < 8; nb++) {
            int m0 = hh * 128 + pbase + mrow;
            int co = nb * 8 + qcol;
            *(float2*)&smf[m0 * EPI_PAD + co]       = make_float2(c[hh][nb][0], c[hh][nb][1]);
            *(float2*)&smf[(m0 + 8) * EPI_PAD + co] = make_float2(c[hh][nb][2], c[hh][nb][3]);
        }
    __syncthreads();

    for (int i = tid; i < 256 * 16; i += 256) {
        int pix = i >> 4, k4 = i & 15;
        float4 v = *(float4*)&smf[pix * EPI_PAD + k4 * 4];
        int cc4 = k4 * 4;
        v.x += __ldg(cb + cc4 + 0);
        v.y += __ldg(cb + cc4 + 1);
        v.z += __ldg(cb + cc4 + 2);
        v.w += __ldg(cb + cc4 + 3);
        int gh = h0 + (pix >> 7);
        int gw = w0 + (pix & 127);
        *(float4*)(g_xconv + (((size_t)b * HH + gh) * WW + gw) * CC + cc4) = v;
    }
}

// ---------------------------------------------------------------------------
// k2: fused depthwise-diag conv + group stats + gate + residual + LSE
//   Staging vectorized: LDG.128 per (pixel, 4ci), scatter STS into [ci][341]
// ---------------------------------------------------------------------------
#define TW 32
#define TH 8
#define HALO_W (TW + 2)
#define HALO_H (TH + 2)
#define XTILE_RAW (HALO_W * HALO_H)        // 340
#define XTILE 341                           // odd stride: conflict-free
#define XS_FLOATS (CC * XTILE)

extern "C" __global__ void __launch_bounds__(256, 2)
k2_fused(const float* __restrict__ w,
         const float* __restrict__ cb,
         const float* __restrict__ gscale,
         const float* __restrict__ gbias,
         float* __restrict__ out)
{
    extern __shared__ float smemf[];
    float* xs  = smemf;
    float* wd  = smemf + XS_FLOATS;
    float* cbs = wd + CC * 9;
    float* gss = cbs + CC;
    float* gbs = gss + CC;

    const int tid = threadIdx.x;
    const int b  = blockIdx.z;
    const int h0 = blockIdx.y * TH;
    const int w0 = blockIdx.x * TW;

    const float* xb = g_xconv + (size_t)b * HH * WW * CC;
    // vectorized staging: 5440 float4 chunks = (pix, 4ci)
    for (int i = tid; i < XTILE_RAW * (CC / 4); i += 256) {
        int pix = i >> 4;                 // /16 chunks per pixel
        int c4  = (i & 15) * 4;
        int row = pix / HALO_W;
        int col = pix - row * HALO_W;
        int gh = h0 + row - 1;
        int gw = w0 + col - 1;
        float4 v = make_float4(0.f, 0.f, 0.f, 0.f);
        if ((unsigned)gh < (unsigned)HH && (unsigned)gw < (unsigned)WW)
            v = *(const float4*)(xb + ((size_t)gh * WW + gw) * CC + c4);
        xs[(c4 + 0) * XTILE + pix] = v.x;
        xs[(c4 + 1) * XTILE + pix] = v.y;
        xs[(c4 + 2) * XTILE + pix] = v.z;
        xs[(c4 + 3) * XTILE + pix] = v.w;
    }
    for (int i = tid; i < CC * 9; i += 256) {
        int cch = i / 9, tap = i - 9 * (i / 9);
        wd[i] = __ldg(w + (size_t)cch * (CC * 9) + cch * 9 + tap);
    }
    if (tid < CC) {
        cbs[tid] = cb[tid];
        gss[tid] = gscale[tid];
        gbs[tid] = gbias[tid];
    }
    __syncthreads();

    const int lx = tid & 31;
    const int ly = tid >> 5;
    const int center = (ly + 1) * HALO_W + (lx + 1);

    float m = -1e30f;
#pragma unroll
    for (int cch = 0; cch < CC; cch++)
        m = fmaxf(m, xs[cch * XTILE + center]);
    m += 1.0f;

    float s = 0.f;
    for (int g = 0; g < GG; g++) {
        float xc[GS];
        float sum = 0.f;
#pragma unroll
        for (int j = 0; j < GS; j++) {
            xc[j] = xs[(g * GS + j) * XTILE + center];
            sum += xc[j];
        }
        float mean = sum * (1.0f / GS);
        float vs = 0.f;
#pragma unroll
        for (int j = 0; j < GS; j++) {
            float dd = xc[j] - mean;
            vs = fmaf(dd, dd, vs);
        }
        float inv = rsqrtf(vs * (1.0f / GS) + 1e-5f);

#pragma unroll
        for (int j = 0; j < GS; j++) {
            int cch = g * GS + j;
            const float* xcp = xs + cch * XTILE;
            const float* wdp = wd + cch * 9;
            float a = cbs[cch];
#pragma unroll
            for (int t = 0; t < 9; t++) {
                int dy = t / 3, dx = t - 3 * (t / 3);
                a = fmaf(wdp[t], xcp[(ly + dy) * HALO_W + (lx + dx)], a);
            }
            float norm = (a - mean) * inv * gss[cch] + gbs[cch];
            float gate = __saturatef(norm * (1.0f / 6.0f) + 0.5f);
            float th;
            asm("tanh.approx.f32 %0, %1;" : "=f"(th) : "f"(norm));
            float v = xc[j] + th * gate;
            s += __expf(v - m);
        }
    }

    out[((size_t)b << 16) + (h0 + ly) * WW + (w0 + lx)] = m + __logf(s);
}

// ---------------------------------------------------------------------------
extern "C" void kernel_launch(void* const* d_in, const int* in_sizes, int n_in,
                              void* d_out, int out_size)
{
    const float* x   = (const float*)d_in[0];
    const float* w   = (const float*)d_in[1];
    const float* cb  = (const float*)d_in[2];
    const float* gsc = (const float*)d_in[3];
    const float* gbi = (const float*)d_in[4];
    float* out = (float*)d_out;

    cudaFuncSetAttribute(k0_xconv, cudaFuncAttributeMaxDynamicSharedMemorySize, K0X_SMEM);
    cudaFuncSetAttribute(k1_conv,  cudaFuncAttributeMaxDynamicSharedMemorySize, SMEM1);
    const int smem2 = (XS_FLOATS + CC * 9 + 3 * CC) * sizeof(float);
    cudaFuncSetAttribute(k2_fused, cudaFuncAttributeMaxDynamicSharedMemorySize, smem2);

    k0_wconv<<<dim3(9, 2), 256>>>(w);
    k0_xconv<<<BB * HH, 256, K0X_SMEM>>>(x);

    dim3 grid1(2, 128, BB);
    k1_conv<<<grid1, 256, SMEM1>>>(cb);

    dim3 grid2(WW / TW, HH / TH, BB);
    k2_fused<<<grid2, 256, smem2>>>(w, cb, gsc, gbi, out);
}

// round 12
// speedup vs baseline: 2.3630x; 1.1873x over previous
#include <cuda_runtime.h>
#include <cuda_fp16.h>
#include <cstdint>

// Problem constants
#define BB 16
#define CC 64
#define HH 256
#define WW 256
#define GG 8
#define GS 8

// ---------------- k1 tiling ----------------
// CTA tile: M=256 px x N=64 couts, K = 9 taps x 64 cin, fp16 A-split (x=xh+xl, w=wh).
#define A_ROWS (4 * 130)
#define A_BYTES (A_ROWS * 128)             // 66560
#define B_OFF A_BYTES
#define B_TAP 8192
#define SMEM1 (B_OFF + 2 * B_TAP)          // 82944
#define EPI_PAD 68
#define K0X_SMEM (256 * EPI_PAD * 4)       // 69632

// Big device buffers (bss, not allocations)
__device__ float g_xconv[(size_t)BB * HH * WW * CC];             // [b][h][w][c]
__device__ __align__(16) __half g_xth[(size_t)BB * HH * WW * CC]; // x hi fp16 [b][h][w][c]
__device__ __align__(16) __half g_xtl[(size_t)BB * HH * WW * CC]; // x lo fp16
__device__ __align__(16) __half g_wsw[9][CC * CC];                // wh fp16 [tap][co][ci] swizzled

__device__ __forceinline__ uint32_t smem_u32(const void* p) {
    uint32_t a;
    asm("{ .reg .u64 t; cvta.to.shared.u64 t, %1; cvt.u32.u64 %0, t; }" : "=r"(a) : "l"(p));
    return a;
}
__device__ __forceinline__ void ldsm4(uint32_t* r, uint32_t addr) {
    asm volatile("ldmatrix.sync.aligned.m8n8.x4.shared.b16 {%0,%1,%2,%3}, [%4];"
                 : "=r"(r[0]), "=r"(r[1]), "=r"(r[2]), "=r"(r[3]) : "r"(addr));
}
__device__ __forceinline__ void hmma(float* c, const uint32_t* a, const uint32_t* b) {
    asm volatile(
        "mma.sync.aligned.m16n8k16.row.col.f32.f16.f16.f32 "
        "{%0,%1,%2,%3}, {%4,%5,%6,%7}, {%8,%9}, {%0,%1,%2,%3};"
        : "+f"(c[0]), "+f"(c[1]), "+f"(c[2]), "+f"(c[3])
        : "r"(a[0]), "r"(a[1]), "r"(a[2]), "r"(a[3]), "r"(b[0]), "r"(b[1]));
}
__device__ __forceinline__ void cpa16(uint32_t dst, const void* src, int szbytes) {
    asm volatile("cp.async.ca.shared.global [%0], [%1], 16, %2;"
                 :: "r"(dst), "l"(src), "r"(szbytes) : "memory");
}
#define CPA_COMMIT() asm volatile("cp.async.commit_group;" ::: "memory")
#define CPA_WAIT0()  asm volatile("cp.async.wait_group 0;" ::: "memory")

// ---------------------------------------------------------------------------
// k0w: weights -> fp16 (single term), layout [tap][co][ci] with chunk swizzle
// ---------------------------------------------------------------------------
extern "C" __global__ void k0_wconv(const float* __restrict__ w)
{
    int tap = blockIdx.x;
    for (int i = threadIdx.x; i < CC * CC; i += 256) {
        int co = i >> 6, ci = i & 63;
        float v = w[(size_t)(co * CC + ci) * 9 + tap];
        uint32_t byte = (uint32_t)co * 128 + ((((uint32_t)ci >> 3) ^ ((uint32_t)co & 7)) << 4)
                      + ((uint32_t)ci & 7) * 2;
        g_wsw[tap][byte >> 1] = __float2half(v);
    }
}

// ---------------------------------------------------------------------------
// k0x: transpose x [b][c][h][w] f32 -> [b][h][w][c] fp16 hi and lo
// ---------------------------------------------------------------------------
extern "C" __global__ void __launch_bounds__(256, 1)
k0_xconv(const float* __restrict__ x)
{
    extern __shared__ uint32_t shp[];   // [256 pix][68] packed {hi, lo<<16}
    const int tid = threadIdx.x;
    const int b = blockIdx.x >> 8;
    const int h = blockIdx.x & 255;
    const float* xr = x + ((size_t)b * CC * HH + h) * WW;

    for (int c = 0; c < CC; c++) {
        float v = xr[(size_t)c * HH * WW + tid];
        __half hi = __float2half(v);
        __half lo = __float2half(v - __half2float(hi));
        uint32_t p = (uint32_t)__half_as_ushort(hi)
                   | ((uint32_t)__half_as_ushort(lo) << 16);
        shp[tid * EPI_PAD + c] = p;
    }
    __syncthreads();

    __half* oh = g_xth + (((size_t)b * HH + h) * WW) * CC;
    __half* ol = g_xtl + (((size_t)b * HH + h) * WW) * CC;
    for (int i = tid; i < 256 * 16; i += 256) {
        int pix = i >> 4, k4 = i & 15;
        uint4 q = *(const uint4*)&shp[pix * EPI_PAD + k4 * 4];
        uint2 hv, lv;
        hv.x = (q.x & 0xFFFFu) | (q.y << 16);
        hv.y = (q.z & 0xFFFFu) | (q.w << 16);
        lv.x = (q.x >> 16) | (q.y & 0xFFFF0000u);
        lv.y = (q.z >> 16) | (q.w & 0xFFFF0000u);
        *(uint2*)(oh + (size_t)pix * CC + k4 * 4) = hv;
        *(uint2*)(ol + (size_t)pix * CC + k4 * 4) = lv;
    }
}

// ---------------------------------------------------------------------------
// k1: conv3x3 + bias via mma.sync fp16 (A-split, single-term W)
//   18 passes: 0-8 A=xh, 9-17 A=xl; B=wh[tap] streamed double-buffered.
//   grid (2, 128, 16); 256 threads; 2 CTAs/SM
// ---------------------------------------------------------------------------
extern "C" __global__ void __launch_bounds__(256, 2)
k1_conv(const float* __restrict__ cb)
{
    extern __shared__ char smem[];
    const uint32_t sA = smem_u32(smem);
    const int tid = threadIdx.x;
    const int wid = tid >> 5;
    const int lid = tid & 31;

    const int b  = blockIdx.z;
    const int h0 = blockIdx.y * 2;
    const int w0 = blockIdx.x * 128;

    const int am  = lid & 15;
    const int akh = (lid >> 4) & 1;
    const int bco = (lid & 7) + ((lid >= 16) ? 8 : 0);
    const int bkh = (lid >> 3) & 1;
    const int pbase = wid * 16;

    auto stageA = [&](const __half* xt) {
        for (int i = tid; i < A_ROWS * 8; i += 256) {
            int rs = i >> 3, chunk = i & 7;
            int R  = rs / 130;
            int px = rs - R * 130;
            int gh = h0 - 1 + R;
            int gw = w0 - 1 + px;
            bool ok = ((unsigned)gh < (unsigned)HH) && ((unsigned)gw < (unsigned)WW);
            const __half* src = xt + ((((size_t)b * HH + gh) * WW + gw) * CC) + chunk * 8;
            uint32_t dst = sA + rs * 128 + ((chunk ^ (rs & 7)) << 4);
            cpa16(dst, src, ok ? 16 : 0);
        }
    };
    auto stageB = [&](int buf, int tap) {
        uint32_t dst = sA + B_OFF + buf * B_TAP;
        const char* s0 = (const char*)&g_wsw[tap][0];
        for (int i = tid; i < B_TAP / 16; i += 256)
            cpa16(dst + i * 16, s0 + i * 16, 16);
    };

    float c[2][8][4];
#pragma unroll
    for (int hh = 0; hh < 2; hh++)
#pragma unroll
        for (int nb = 0; nb < 8; nb++)
#pragma unroll
            for (int q = 0; q < 4; q++) c[hh][nb][q] = 0.f;

    stageA(g_xth);
    stageB(0, 0);
    CPA_COMMIT();

    int cur = 0;
    for (int pass = 0; pass < 18; pass++) {
        CPA_WAIT0();
        __syncthreads();

        if (pass < 17 && pass != 8) {
            int np = pass + 1;
            int ntap = (np < 9) ? np : np - 9;
            stageB(cur ^ 1, ntap);
            CPA_COMMIT();
        }

        const int tap = (pass < 9) ? pass : pass - 9;
        const int dy = tap / 3, dx = tap - 3 * (tap / 3);
        const uint32_t sBc = sA + B_OFF + cur * B_TAP + bco * 128;

#pragma unroll
        for (int kb = 0; kb < 4; kb++) {
            uint32_t a[2][4];
#pragma unroll
            for (int hh = 0; hh < 2; hh++) {
                int rs = (hh + dy) * 130 + pbase + dx + am;
                uint32_t addr = sA + rs * 128
                              + ((((uint32_t)(kb * 2 + akh)) ^ (rs & 7)) << 4);
                ldsm4(a[hh], addr);
            }
            uint32_t bbf[4][4];
#pragma unroll
            for (int j = 0; j < 4; j++) {
                uint32_t co = (uint32_t)(j * 16 + bco);
                uint32_t addr = sBc + j * 16 * 128
                              + ((((uint32_t)(kb * 2 + bkh)) ^ (co & 7)) << 4);
                ldsm4(bbf[j], addr);
            }
#pragma unroll
            for (int hh = 0; hh < 2; hh++)
#pragma unroll
                for (int j = 0; j < 4; j++) {
                    hmma(c[hh][2 * j + 0], a[hh], &bbf[j][0]);
                    hmma(c[hh][2 * j + 1], a[hh], &bbf[j][2]);
                }
        }

        if (pass == 8) {
            __syncthreads();
            stageA(g_xtl);
            stageB(cur ^ 1, 0);
            CPA_COMMIT();
        }
        cur ^= 1;
    }

    // ---- epilogue ----
    __syncthreads();
    float* smf = (float*)smem;
    const int mrow = (lid >> 2);
    const int qcol = (lid & 3) * 2;
#pragma unroll
    for (int hh = 0; hh < 2; hh++)
#pragma unroll
        for (int nb = 0; nb < 8; nb++) {
            int m0 = hh * 128 + pbase + mrow;
            int co = nb * 8 + qcol;
            *(float2*)&smf[m0 * EPI_PAD + co]       = make_float2(c[hh][nb][0], c[hh][nb][1]);
            *(float2*)&smf[(m0 + 8) * EPI_PAD + co] = make_float2(c[hh][nb][2], c[hh][nb][3]);
        }
    __syncthreads();

    for (int i = tid; i < 256 * 16; i += 256) {
        int pix = i >> 4, k4 = i & 15;
        float4 v = *(float4*)&smf[pix * EPI_PAD + k4 * 4];
        int cc4 = k4 * 4;
        v.x += __ldg(cb + cc4 + 0);
        v.y += __ldg(cb + cc4 + 1);
        v.z += __ldg(cb + cc4 + 2);
        v.w += __ldg(cb + cc4 + 3);
        int gh = h0 + (pix >> 7);
        int gw = w0 + (pix & 127);
        *(float4*)(g_xconv + (((size_t)b * HH + gh) * WW + gw) * CC + cc4) = v;
    }
}

// ---------------------------------------------------------------------------
// k2: fused depthwise-diag conv + group stats + gate + residual + LSE
//   (unchanged from R11: vectorized staging, odd-stride smem, HW tanh)
// ---------------------------------------------------------------------------
#define TW 32
#define TH 8
#define HALO_W (TW + 2)
#define HALO_H (TH + 2)
#define XTILE_RAW (HALO_W * HALO_H)        // 340
#define XTILE 341                           // odd stride: conflict-free
#define XS_FLOATS (CC * XTILE)

extern "C" __global__ void __launch_bounds__(256, 2)
k2_fused(const float* __restrict__ w,
         const float* __restrict__ cb,
         const float* __restrict__ gscale,
         const float* __restrict__ gbias,
         float* __restrict__ out)
{
    extern __shared__ float smemf[];
    float* xs  = smemf;
    float* wd  = smemf + XS_FLOATS;
    float* cbs = wd + CC * 9;
    float* gss = cbs + CC;
    float* gbs = gss + CC;

    const int tid = threadIdx.x;
    const int b  = blockIdx.z;
    const int h0 = blockIdx.y * TH;
    const int w0 = blockIdx.x * TW;

    const float* xb = g_xconv + (size_t)b * HH * WW * CC;
    for (int i = tid; i < XTILE_RAW * (CC / 4); i += 256) {
        int pix = i >> 4;
        int c4  = (i & 15) * 4;
        int row = pix / HALO_W;
        int col = pix - row * HALO_W;
        int gh = h0 + row - 1;
        int gw = w0 + col - 1;
        float4 v = make_float4(0.f, 0.f, 0.f, 0.f);
        if ((unsigned)gh < (unsigned)HH && (unsigned)gw < (unsigned)WW)
            v = *(const float4*)(xb + ((size_t)gh * WW + gw) * CC + c4);
        xs[(c4 + 0) * XTILE + pix] = v.x;
        xs[(c4 + 1) * XTILE + pix] = v.y;
        xs[(c4 + 2) * XTILE + pix] = v.z;
        xs[(c4 + 3) * XTILE + pix] = v.w;
    }
    for (int i = tid; i < CC * 9; i += 256) {
        int cch = i / 9, tap = i - 9 * (i / 9);
        wd[i] = __ldg(w + (size_t)cch * (CC * 9) + cch * 9 + tap);
    }
    if (tid < CC) {
        cbs[tid] = cb[tid];
        gss[tid] = gscale[tid];
        gbs[tid] = gbias[tid];
    }
    __syncthreads();

    const int lx = tid & 31;
    const int ly = tid >> 5;
    const int center = (ly + 1) * HALO_W + (lx + 1);

    float m = -1e30f;
#pragma unroll
    for (int cch = 0; cch < CC; cch++)
        m = fmaxf(m, xs[cch * XTILE + center]);
    m += 1.0f;

    float s = 0.f;
    for (int g = 0; g < GG; g++) {
        float xc[GS];
        float sum = 0.f;
#pragma unroll
        for (int j = 0; j < GS; j++) {
            xc[j] = xs[(g * GS + j) * XTILE + center];
            sum += xc[j];
        }
        float mean = sum * (1.0f / GS);
        float vs = 0.f;
#pragma unroll
        for (int j = 0; j < GS; j++) {
            float dd = xc[j] - mean;
            vs = fmaf(dd, dd, vs);
        }
        float inv = rsqrtf(vs * (1.0f / GS) + 1e-5f);

#pragma unroll
        for (int j = 0; j < GS; j++) {
            int cch = g * GS + j;
            const float* xcp = xs + cch * XTILE;
            const float* wdp = wd + cch * 9;
            float a = cbs[cch];
#pragma unroll
            for (int t = 0; t < 9; t++) {
                int dy = t / 3, dx = t - 3 * (t / 3);
                a = fmaf(wdp[t], xcp[(ly + dy) * HALO_W + (lx + dx)], a);
            }
            float norm = (a - mean) * inv * gss[cch] + gbs[cch];
            float gate = __saturatef(norm * (1.0f / 6.0f) + 0.5f);
            float th;
            asm("tanh.approx.f32 %0, %1;" : "=f"(th) : "f"(norm));
            float v = xc[j] + th * gate;
            s += __expf(v - m);
        }
    }

    out[((size_t)b << 16) + (h0 + ly) * WW + (w0 + lx)] = m + __logf(s);
}

// ---------------------------------------------------------------------------
extern "C" void kernel_launch(void* const* d_in, const int* in_sizes, int n_in,
                              void* d_out, int out_size)
{
    const float* x   = (const float*)d_in[0];
    const float* w   = (const float*)d_in[1];
    const float* cb  = (const float*)d_in[2];
    const float* gsc = (const float*)d_in[3];
    const float* gbi = (const float*)d_in[4];
    float* out = (float*)d_out;

    cudaFuncSetAttribute(k0_xconv, cudaFuncAttributeMaxDynamicSharedMemorySize, K0X_SMEM);
    cudaFuncSetAttribute(k1_conv,  cudaFuncAttributeMaxDynamicSharedMemorySize, SMEM1);
    const int smem2 = (XS_FLOATS + CC * 9 + 3 * CC) * sizeof(float);
    cudaFuncSetAttribute(k2_fused, cudaFuncAttributeMaxDynamicSharedMemorySize, smem2);

    k0_wconv<<<9, 256>>>(w);
    k0_xconv<<<BB * HH, 256, K0X_SMEM>>>(x);

    dim3 grid1(2, 128, BB);
    k1_conv<<<grid1, 256, SMEM1>>>(cb);

    dim3 grid2(WW / TW, HH / TH, BB);
    k2_fused<<<grid2, 256, smem2>>>(w, cb, gsc, gbi, out);
}

// round 13
// speedup vs baseline: 3.4190x; 1.4469x over previous
#include <cuda_runtime.h>
#include <cuda_fp16.h>
#include <cstdint>

// Problem constants
#define BB 16
#define CC 64
#define HH 256
#define WW 256
#define GG 8
#define GS 8

// ---------------- k1 tiling ----------------
// CTA tile: M=256 px x N=64 couts, K = 9 taps x 64 cin, single-term fp16.
#define A_ROWS (4 * 130)
#define A_BYTES (A_ROWS * 128)             // 66560
#define B_OFF A_BYTES
#define B_TAP 8192
#define SMEM1 (B_OFF + 2 * B_TAP)          // 82944
#define EPI_PAD 68
#define K0X_SMEM (256 * EPI_PAD * 4)       // 69632

// Big device buffers (bss, not allocations)
__device__ float g_xconv[(size_t)BB * HH * WW * CC];              // [b][h][w][c]
__device__ __align__(16) __half g_xth[(size_t)BB * HH * WW * CC]; // x fp16 [b][h][w][c]
__device__ __align__(16) __half g_wsw[9][CC * CC];                // w fp16 [tap][co][ci] swizzled

__device__ __forceinline__ uint32_t smem_u32(const void* p) {
    uint32_t a;
    asm("{ .reg .u64 t; cvta.to.shared.u64 t, %1; cvt.u32.u64 %0, t; }" : "=r"(a) : "l"(p));
    return a;
}
__device__ __forceinline__ void ldsm4(uint32_t* r, uint32_t addr) {
    asm volatile("ldmatrix.sync.aligned.m8n8.x4.shared.b16 {%0,%1,%2,%3}, [%4];"
                 : "=r"(r[0]), "=r"(r[1]), "=r"(r[2]), "=r"(r[3]) : "r"(addr));
}
__device__ __forceinline__ void hmma(float* c, const uint32_t* a, const uint32_t* b) {
    asm volatile(
        "mma.sync.aligned.m16n8k16.row.col.f32.f16.f16.f32 "
        "{%0,%1,%2,%3}, {%4,%5,%6,%7}, {%8,%9}, {%0,%1,%2,%3};"
        : "+f"(c[0]), "+f"(c[1]), "+f"(c[2]), "+f"(c[3])
        : "r"(a[0]), "r"(a[1]), "r"(a[2]), "r"(a[3]), "r"(b[0]), "r"(b[1]));
}
__device__ __forceinline__ void cpa16(uint32_t dst, const void* src, int szbytes) {
    asm volatile("cp.async.ca.shared.global [%0], [%1], 16, %2;"
                 :: "r"(dst), "l"(src), "r"(szbytes) : "memory");
}
#define CPA_COMMIT() asm volatile("cp.async.commit_group;" ::: "memory")
#define CPA_WAIT0()  asm volatile("cp.async.wait_group 0;" ::: "memory")

// ---------------------------------------------------------------------------
// k0w: weights -> fp16, layout [tap][co][ci] with 16B-chunk swizzle
// ---------------------------------------------------------------------------
extern "C" __global__ void k0_wconv(const float* __restrict__ w)
{
    int tap = blockIdx.x;
    for (int i = threadIdx.x; i < CC * CC; i += 256) {
        int co = i >> 6, ci = i & 63;
        float v = w[(size_t)(co * CC + ci) * 9 + tap];
        uint32_t byte = (uint32_t)co * 128 + ((((uint32_t)ci >> 3) ^ ((uint32_t)co & 7)) << 4)
                      + ((uint32_t)ci & 7) * 2;
        g_wsw[tap][byte >> 1] = __float2half(v);
    }
}

// ---------------------------------------------------------------------------
// k0x: transpose x [b][c][h][w] f32 -> [b][h][w][c] fp16 (single term)
// ---------------------------------------------------------------------------
extern "C" __global__ void __launch_bounds__(256, 1)
k0_xconv(const float* __restrict__ x)
{
    extern __shared__ uint32_t shp[];   // [256 pix][68] fp16 in low half
    const int tid = threadIdx.x;
    const int b = blockIdx.x >> 8;
    const int h = blockIdx.x & 255;
    const float* xr = x + ((size_t)b * CC * HH + h) * WW;

    for (int c = 0; c < CC; c++) {
        float v = xr[(size_t)c * HH * WW + tid];
        shp[tid * EPI_PAD + c] = (uint32_t)__half_as_ushort(__float2half(v));
    }
    __syncthreads();

    __half* oh = g_xth + (((size_t)b * HH + h) * WW) * CC;
    for (int i = tid; i < 256 * 16; i += 256) {
        int pix = i >> 4, k4 = i & 15;
        uint4 q = *(const uint4*)&shp[pix * EPI_PAD + k4 * 4];
        uint2 hv;
        hv.x = (q.x & 0xFFFFu) | (q.y << 16);
        hv.y = (q.z & 0xFFFFu) | (q.w << 16);
        *(uint2*)(oh + (size_t)pix * CC + k4 * 4) = hv;
    }
}

// ---------------------------------------------------------------------------
// k1: conv3x3 + bias via mma.sync fp16 (single term), out [b][h][w][c]
//   9 tap-passes, B streamed double-buffered, A staged once.
//   grid (2, 128, 16); 256 threads; 2 CTAs/SM
// ---------------------------------------------------------------------------
extern "C" __global__ void __launch_bounds__(256, 2)
k1_conv(const float* __restrict__ cb)
{
    extern __shared__ char smem[];
    const uint32_t sA = smem_u32(smem);
    const int tid = threadIdx.x;
    const int wid = tid >> 5;
    const int lid = tid & 31;

    const int b  = blockIdx.z;
    const int h0 = blockIdx.y * 2;
    const int w0 = blockIdx.x * 128;

    const int am  = lid & 15;
    const int akh = (lid >> 4) & 1;
    const int bco = (lid & 7) + ((lid >= 16) ? 8 : 0);
    const int bkh = (lid >> 3) & 1;
    const int pbase = wid * 16;

    // ---- stage A (once) ----
    for (int i = tid; i < A_ROWS * 8; i += 256) {
        int rs = i >> 3, chunk = i & 7;
        int R  = rs / 130;
        int px = rs - R * 130;
        int gh = h0 - 1 + R;
        int gw = w0 - 1 + px;
        bool ok = ((unsigned)gh < (unsigned)HH) && ((unsigned)gw < (unsigned)WW);
        const __half* src = g_xth + ((((size_t)b * HH + gh) * WW + gw) * CC) + chunk * 8;
        uint32_t dst = sA + rs * 128 + ((chunk ^ (rs & 7)) << 4);
        cpa16(dst, src, ok ? 16 : 0);
    }
    auto stageB = [&](int buf, int tap) {
        uint32_t dst = sA + B_OFF + buf * B_TAP;
        const char* s0 = (const char*)&g_wsw[tap][0];
        for (int i = tid; i < B_TAP / 16; i += 256)
            cpa16(dst + i * 16, s0 + i * 16, 16);
    };

    float c[2][8][4];
#pragma unroll
    for (int hh = 0; hh < 2; hh++)
#pragma unroll
        for (int nb = 0; nb < 8; nb++)
#pragma unroll
            for (int q = 0; q < 4; q++) c[hh][nb][q] = 0.f;

    stageB(0, 0);
    CPA_COMMIT();

    int cur = 0;
    for (int tap = 0; tap < 9; tap++) {
        CPA_WAIT0();
        __syncthreads();

        if (tap < 8) {
            stageB(cur ^ 1, tap + 1);
            CPA_COMMIT();
        }

        const int dy = tap / 3, dx = tap - 3 * (tap / 3);
        const uint32_t sBc = sA + B_OFF + cur * B_TAP + bco * 128;

#pragma unroll
        for (int kb = 0; kb < 4; kb++) {
            uint32_t a[2][4];
#pragma unroll
            for (int hh = 0; hh < 2; hh++) {
                int rs = (hh + dy) * 130 + pbase + dx + am;
                uint32_t addr = sA + rs * 128
                              + ((((uint32_t)(kb * 2 + akh)) ^ (rs & 7)) << 4);
                ldsm4(a[hh], addr);
            }
            uint32_t bbf[4][4];
#pragma unroll
            for (int j = 0; j < 4; j++) {
                uint32_t co = (uint32_t)(j * 16 + bco);
                uint32_t addr = sBc + j * 16 * 128
                              + ((((uint32_t)(kb * 2 + bkh)) ^ (co & 7)) << 4);
                ldsm4(bbf[j], addr);
            }
#pragma unroll
            for (int hh = 0; hh < 2; hh++)
#pragma unroll
                for (int j = 0; j < 4; j++) {
                    hmma(c[hh][2 * j + 0], a[hh], &bbf[j][0]);
                    hmma(c[hh][2 * j + 1], a[hh], &bbf[j][2]);
                }
        }
        cur ^= 1;
    }

    // ---- epilogue ----
    __syncthreads();
    float* smf = (float*)smem;
    const int mrow = (lid >> 2);
    const int qcol = (lid & 3) * 2;
#pragma unroll
    for (int hh = 0; hh < 2; hh++)
#pragma unroll
        for (int nb = 0; nb < 8; nb++) {
            int m0 = hh * 128 + pbase + mrow;
            int co = nb * 8 + qcol;
            *(float2*)&smf[m0 * EPI_PAD + co]       = make_float2(c[hh][nb][0], c[hh][nb][1]);
            *(float2*)&smf[(m0 + 8) * EPI_PAD + co] = make_float2(c[hh][nb][2], c[hh][nb][3]);
        }
    __syncthreads();

    for (int i = tid; i < 256 * 16; i += 256) {
        int pix = i >> 4, k4 = i & 15;
        float4 v = *(float4*)&smf[pix * EPI_PAD + k4 * 4];
        int cc4 = k4 * 4;
        v.x += __ldg(cb + cc4 + 0);
        v.y += __ldg(cb + cc4 + 1);
        v.z += __ldg(cb + cc4 + 2);
        v.w += __ldg(cb + cc4 + 3);
        int gh = h0 + (pix >> 7);
        int gw = w0 + (pix & 127);
        *(float4*)(g_xconv + (((size_t)b * HH + gh) * WW + gw) * CC + cc4) = v;
    }
}

// ---------------------------------------------------------------------------
// k2: fused depthwise-diag conv + group stats + gate + residual + LSE
//   (unchanged from R11/R12)
// ---------------------------------------------------------------------------
#define TW 32
#define TH 8
#define HALO_W (TW + 2)
#define HALO_H (TH + 2)
#define XTILE_RAW (HALO_W * HALO_H)        // 340
#define XTILE 341                           // odd stride: conflict-free
#define XS_FLOATS (CC * XTILE)

extern "C" __global__ void __launch_bounds__(256, 2)
k2_fused(const float* __restrict__ w,
         const float* __restrict__ cb,
         const float* __restrict__ gscale,
         const float* __restrict__ gbias,
         float* __restrict__ out)
{
    extern __shared__ float smemf[];
    float* xs  = smemf;
    float* wd  = smemf + XS_FLOATS;
    float* cbs = wd + CC * 9;
    float* gss = cbs + CC;
    float* gbs = gss + CC;

    const int tid = threadIdx.x;
    const int b  = blockIdx.z;
    const int h0 = blockIdx.y * TH;
    const int w0 = blockIdx.x * TW;

    const float* xb = g_xconv + (size_t)b * HH * WW * CC;
    for (int i = tid; i < XTILE_RAW * (CC / 4); i += 256) {
        int pix = i >> 4;
        int c4  = (i & 15) * 4;
        int row = pix / HALO_W;
        int col = pix - row * HALO_W;
        int gh = h0 + row - 1;
        int gw = w0 + col - 1;
        float4 v = make_float4(0.f, 0.f, 0.f, 0.f);
        if ((unsigned)gh < (unsigned)HH && (unsigned)gw < (unsigned)WW)
            v = *(const float4*)(xb + ((size_t)gh * WW + gw) * CC + c4);
        xs[(c4 + 0) * XTILE + pix] = v.x;
        xs[(c4 + 1) * XTILE + pix] = v.y;
        xs[(c4 + 2) * XTILE + pix] = v.z;
        xs[(c4 + 3) * XTILE + pix] = v.w;
    }
    for (int i = tid; i < CC * 9; i += 256) {
        int cch = i / 9, tap = i - 9 * (i / 9);
        wd[i] = __ldg(w + (size_t)cch * (CC * 9) + cch * 9 + tap);
    }
    if (tid < CC) {
        cbs[tid] = cb[tid];
        gss[tid] = gscale[tid];
        gbs[tid] = gbias[tid];
    }
    __syncthreads();

    const int lx = tid & 31;
    const int ly = tid >> 5;
    const int center = (ly + 1) * HALO_W + (lx + 1);

    float m = -1e30f;
#pragma unroll
    for (int cch = 0; cch < CC; cch++)
        m = fmaxf(m, xs[cch * XTILE + center]);
    m += 1.0f;

    float s = 0.f;
    for (int g = 0; g < GG; g++) {
        float xc[GS];
        float sum = 0.f;
#pragma unroll
        for (int j = 0; j < GS; j++) {
            xc[j] = xs[(g * GS + j) * XTILE + center];
            sum += xc[j];
        }
        float mean = sum * (1.0f / GS);
        float vs = 0.f;
#pragma unroll
        for (int j = 0; j < GS; j++) {
            float dd = xc[j] - mean;
            vs = fmaf(dd, dd, vs);
        }
        float inv = rsqrtf(vs * (1.0f / GS) + 1e-5f);

#pragma unroll
        for (int j = 0; j < GS; j++) {
            int cch = g * GS + j;
            const float* xcp = xs + cch * XTILE;
            const float* wdp = wd + cch * 9;
            float a = cbs[cch];
#pragma unroll
            for (int t = 0; t < 9; t++) {
                int dy = t / 3, dx = t - 3 * (t / 3);
                a = fmaf(wdp[t], xcp[(ly + dy) * HALO_W + (lx + dx)], a);
            }
            float norm = (a - mean) * inv * gss[cch] + gbs[cch];
            float gate = __saturatef(norm * (1.0f / 6.0f) + 0.5f);
            float th;
            asm("tanh.approx.f32 %0, %1;" : "=f"(th) : "f"(norm));
            float v = xc[j] + th * gate;
            s += __expf(v - m);
        }
    }

    out[((size_t)b << 16) + (h0 + ly) * WW + (w0 + lx)] = m + __logf(s);
}

// ---------------------------------------------------------------------------
extern "C" void kernel_launch(void* const* d_in, const int* in_sizes, int n_in,
                              void* d_out, int out_size)
{
    const float* x   = (const float*)d_in[0];
    const float* w   = (const float*)d_in[1];
    const float* cb  = (const float*)d_in[2];
    const float* gsc = (const float*)d_in[3];
    const float* gbi = (const float*)d_in[4];
    float* out = (float*)d_out;

    cudaFuncSetAttribute(k0_xconv, cudaFuncAttributeMaxDynamicSharedMemorySize, K0X_SMEM);
    cudaFuncSetAttribute(k1_conv,  cudaFuncAttributeMaxDynamicSharedMemorySize, SMEM1);
    const int smem2 = (XS_FLOATS + CC * 9 + 3 * CC) * sizeof(float);
    cudaFuncSetAttribute(k2_fused, cudaFuncAttributeMaxDynamicSharedMemorySize, smem2);

    k0_wconv<<<9, 256>>>(w);
    k0_xconv<<<BB * HH, 256, K0X_SMEM>>>(x);

    dim3 grid1(2, 128, BB);
    k1_conv<<<grid1, 256, SMEM1>>>(cb);

    dim3 grid2(WW / TW, HH / TH, BB);
    k2_fused<<<grid2, 256, smem2>>>(w, cb, gsc, gbi, out);
}

// round 14
// speedup vs baseline: 3.6391x; 1.0644x over previous
#include <cuda_runtime.h>
#include <cuda_fp16.h>
#include <cstdint>

// Problem constants
#define BB 16
#define CC 64
#define HH 256
#define WW 256
#define GG 8
#define GS 8

// ---------------- k1 tiling ----------------
#define A_ROWS (4 * 130)
#define A_BYTES (A_ROWS * 128)             // 66560
#define B_OFF A_BYTES
#define B_TAP 8192
#define SMEM1 (B_OFF + 2 * B_TAP)          // 82944
#define EPI_PAD 68
#define K0X_SMEM (256 * EPI_PAD * 4)       // 69632

// Big device buffers (bss, not allocations)
__device__ float g_xconv[(size_t)BB * HH * WW * CC];              // [b][h][w][c]
__device__ __align__(16) __half g_xth[(size_t)BB * HH * WW * CC]; // x fp16 [b][h][w][c]
__device__ __align__(16) __half g_wsw[9][CC * CC];                // w fp16 [tap][co][ci] swizzled

__device__ __forceinline__ uint32_t smem_u32(const void* p) {
    uint32_t a;
    asm("{ .reg .u64 t; cvta.to.shared.u64 t, %1; cvt.u32.u64 %0, t; }" : "=r"(a) : "l"(p));
    return a;
}
__device__ __forceinline__ void ldsm4(uint32_t* r, uint32_t addr) {
    asm volatile("ldmatrix.sync.aligned.m8n8.x4.shared.b16 {%0,%1,%2,%3}, [%4];"
                 : "=r"(r[0]), "=r"(r[1]), "=r"(r[2]), "=r"(r[3]) : "r"(addr));
}
__device__ __forceinline__ void hmma(float* c, const uint32_t* a, const uint32_t* b) {
    asm volatile(
        "mma.sync.aligned.m16n8k16.row.col.f32.f16.f16.f32 "
        "{%0,%1,%2,%3}, {%4,%5,%6,%7}, {%8,%9}, {%0,%1,%2,%3};"
        : "+f"(c[0]), "+f"(c[1]), "+f"(c[2]), "+f"(c[3])
        : "r"(a[0]), "r"(a[1]), "r"(a[2]), "r"(a[3]), "r"(b[0]), "r"(b[1]));
}
__device__ __forceinline__ void cpa16(uint32_t dst, const void* src, int szbytes) {
    asm volatile("cp.async.ca.shared.global [%0], [%1], 16, %2;"
                 :: "r"(dst), "l"(src), "r"(szbytes) : "memory");
}
#define CPA_COMMIT() asm volatile("cp.async.commit_group;" ::: "memory")
#define CPA_WAIT0()  asm volatile("cp.async.wait_group 0;" ::: "memory")

// ---------------------------------------------------------------------------
// k0w: weights -> fp16, layout [tap][co][ci] with 16B-chunk swizzle
// ---------------------------------------------------------------------------
extern "C" __global__ void k0_wconv(const float* __restrict__ w)
{
    int tap = blockIdx.x;
    for (int i = threadIdx.x; i < CC * CC; i += 256) {
        int co = i >> 6, ci = i & 63;
        float v = w[(size_t)(co * CC + ci) * 9 + tap];
        uint32_t byte = (uint32_t)co * 128 + ((((uint32_t)ci >> 3) ^ ((uint32_t)co & 7)) << 4)
                      + ((uint32_t)ci & 7) * 2;
        g_wsw[tap][byte >> 1] = __float2half(v);
    }
}

// ---------------------------------------------------------------------------
// k0x: transpose x [b][c][h][w] f32 -> [b][h][w][c] fp16
// ---------------------------------------------------------------------------
extern "C" __global__ void __launch_bounds__(256, 1)
k0_xconv(const float* __restrict__ x)
{
    extern __shared__ uint32_t shp[];   // [256 pix][68] fp16 in low half
    const int tid = threadIdx.x;
    const int b = blockIdx.x >> 8;
    const int h = blockIdx.x & 255;
    const float* xr = x + ((size_t)b * CC * HH + h) * WW;

    for (int c = 0; c < CC; c++) {
        float v = xr[(size_t)c * HH * WW + tid];
        shp[tid * EPI_PAD + c] = (uint32_t)__half_as_ushort(__float2half(v));
    }
    __syncthreads();

    __half* oh = g_xth + (((size_t)b * HH + h) * WW) * CC;
    for (int i = tid; i < 256 * 16; i += 256) {
        int pix = i >> 4, k4 = i & 15;
        uint4 q = *(const uint4*)&shp[pix * EPI_PAD + k4 * 4];
        uint2 hv;
        hv.x = (q.x & 0xFFFFu) | (q.y << 16);
        hv.y = (q.z & 0xFFFFu) | (q.w << 16);
        *(uint2*)(oh + (size_t)pix * CC + k4 * 4) = hv;
    }
}

// ---------------------------------------------------------------------------
// k1: conv3x3 + bias via mma.sync fp16, out [b][h][w][c]
//   9 tap-passes, B streamed double-buffered, A staged once. (unchanged R13)
// ---------------------------------------------------------------------------
extern "C" __global__ void __launch_bounds__(256, 2)
k1_conv(const float* __restrict__ cb)
{
    extern __shared__ char smem[];
    const uint32_t sA = smem_u32(smem);
    const int tid = threadIdx.x;
    const int wid = tid >> 5;
    const int lid = tid & 31;

    const int b  = blockIdx.z;
    const int h0 = blockIdx.y * 2;
    const int w0 = blockIdx.x * 128;

    const int am  = lid & 15;
    const int akh = (lid >> 4) & 1;
    const int bco = (lid & 7) + ((lid >= 16) ? 8 : 0);
    const int bkh = (lid >> 3) & 1;
    const int pbase = wid * 16;

    for (int i = tid; i < A_ROWS * 8; i += 256) {
        int rs = i >> 3, chunk = i & 7;
        int R  = rs / 130;
        int px = rs - R * 130;
        int gh = h0 - 1 + R;
        int gw = w0 - 1 + px;
        bool ok = ((unsigned)gh < (unsigned)HH) && ((unsigned)gw < (unsigned)WW);
        const __half* src = g_xth + ((((size_t)b * HH + gh) * WW + gw) * CC) + chunk * 8;
        uint32_t dst = sA + rs * 128 + ((chunk ^ (rs & 7)) << 4);
        cpa16(dst, src, ok ? 16 : 0);
    }
    auto stageB = [&](int buf, int tap) {
        uint32_t dst = sA + B_OFF + buf * B_TAP;
        const char* s0 = (const char*)&g_wsw[tap][0];
        for (int i = tid; i < B_TAP / 16; i += 256)
            cpa16(dst + i * 16, s0 + i * 16, 16);
    };

    float c[2][8][4];
#pragma unroll
    for (int hh = 0; hh < 2; hh++)
#pragma unroll
        for (int nb = 0; nb < 8; nb++)
#pragma unroll
            for (int q = 0; q < 4; q++) c[hh][nb][q] = 0.f;

    stageB(0, 0);
    CPA_COMMIT();

    int cur = 0;
    for (int tap = 0; tap < 9; tap++) {
        CPA_WAIT0();
        __syncthreads();

        if (tap < 8) {
            stageB(cur ^ 1, tap + 1);
            CPA_COMMIT();
        }

        const int dy = tap / 3, dx = tap - 3 * (tap / 3);
        const uint32_t sBc = sA + B_OFF + cur * B_TAP + bco * 128;

#pragma unroll
        for (int kb = 0; kb < 4; kb++) {
            uint32_t a[2][4];
#pragma unroll
            for (int hh = 0; hh < 2; hh++) {
                int rs = (hh + dy) * 130 + pbase + dx + am;
                uint32_t addr = sA + rs * 128
                              + ((((uint32_t)(kb * 2 + akh)) ^ (rs & 7)) << 4);
                ldsm4(a[hh], addr);
            }
            uint32_t bbf[4][4];
#pragma unroll
            for (int j = 0; j < 4; j++) {
                uint32_t co = (uint32_t)(j * 16 + bco);
                uint32_t addr = sBc + j * 16 * 128
                              + ((((uint32_t)(kb * 2 + bkh)) ^ (co & 7)) << 4);
                ldsm4(bbf[j], addr);
            }
#pragma unroll
            for (int hh = 0; hh < 2; hh++)
#pragma unroll
                for (int j = 0; j < 4; j++) {
                    hmma(c[hh][2 * j + 0], a[hh], &bbf[j][0]);
                    hmma(c[hh][2 * j + 1], a[hh], &bbf[j][2]);
                }
        }
        cur ^= 1;
    }

    __syncthreads();
    float* smf = (float*)smem;
    const int mrow = (lid >> 2);
    const int qcol = (lid & 3) * 2;
#pragma unroll
    for (int hh = 0; hh < 2; hh++)
#pragma unroll
        for (int nb = 0; nb < 8; nb++) {
            int m0 = hh * 128 + pbase + mrow;
            int co = nb * 8 + qcol;
            *(float2*)&smf[m0 * EPI_PAD + co]       = make_float2(c[hh][nb][0], c[hh][nb][1]);
            *(float2*)&smf[(m0 + 8) * EPI_PAD + co] = make_float2(c[hh][nb][2], c[hh][nb][3]);
        }
    __syncthreads();

    for (int i = tid; i < 256 * 16; i += 256) {
        int pix = i >> 4, k4 = i & 15;
        float4 v = *(float4*)&smf[pix * EPI_PAD + k4 * 4];
        int cc4 = k4 * 4;
        v.x += __ldg(cb + cc4 + 0);
        v.y += __ldg(cb + cc4 + 1);
        v.z += __ldg(cb + cc4 + 2);
        v.w += __ldg(cb + cc4 + 3);
        int gh = h0 + (pix >> 7);
        int gw = w0 + (pix & 127);
        *(float4*)(g_xconv + (((size_t)b * HH + gh) * WW + gw) * CC + cc4) = v;
    }
}

// ---------------------------------------------------------------------------
// k2: fused epilogue, channels-last smem tile [pix][68] (float4 everywhere)
//   - staging: direct cp.async float4 copies (no transpose)
//   - depthwise conv: 9 LDS.128 per 4-channel group, broadcast float4 weights
// ---------------------------------------------------------------------------
#define TW 32
#define TH 8
#define HALO_W (TW + 2)
#define HALO_H (TH + 2)
#define K2_PIX (HALO_W * HALO_H)           // 340
#define K2_PAD 68                           // floats per pixel (64 + 4 pad); 272B, 16B-aligned
#define K2_XS_FLOATS (K2_PIX * K2_PAD)     // 23120
#define K2_WD_OFF K2_XS_FLOATS              // wd4: 16 groups x 9 taps x float4 = 576 floats
#define K2_CB_OFF (K2_WD_OFF + 576)
#define K2_GS_OFF (K2_CB_OFF + CC)
#define K2_GB_OFF (K2_GS_OFF + CC)
#define K2_SMEM_FLOATS (K2_GB_OFF + CC)
#define K2_SMEM_BYTES (K2_SMEM_FLOATS * 4)  // ~95KB -> 2 CTAs/SM

extern "C" __global__ void __launch_bounds__(256, 2)
k2_fused(const float* __restrict__ w,
         const float* __restrict__ cb,
         const float* __restrict__ gscale,
         const float* __restrict__ gbias,
         float* __restrict__ out)
{
    extern __shared__ float smemf[];
    float* xs  = smemf;                 // [340][68]
    float* wd4 = smemf + K2_WD_OFF;     // [(c4*9+t)*4 + k]
    float* cbs = smemf + K2_CB_OFF;
    float* gss = smemf + K2_GS_OFF;
    float* gbs = smemf + K2_GB_OFF;

    const uint32_t sXS = smem_u32(xs);
    const int tid = threadIdx.x;
    const int b  = blockIdx.z;
    const int h0 = blockIdx.y * TH;
    const int w0 = blockIdx.x * TW;

    // ---- stage tile via cp.async: (pix, c4) -> [pix][68] ----
    const float* xb = g_xconv + (size_t)b * HH * WW * CC;
    for (int i = tid; i < K2_PIX * 16; i += 256) {
        int pix = i >> 4;
        int c4  = i & 15;
        int row = pix / HALO_W;
        int col = pix - row * HALO_W;
        int gh = h0 + row - 1;
        int gw = w0 + col - 1;
        bool ok = ((unsigned)gh < (unsigned)HH) && ((unsigned)gw < (unsigned)WW);
        const float* src = xb + ((size_t)gh * WW + gw) * CC + c4 * 4;
        cpa16(sXS + (uint32_t)pix * (K2_PAD * 4) + c4 * 16, src, ok ? 16 : 0);
    }
    CPA_COMMIT();

    // diag weights into float4-friendly layout
    for (int i = tid; i < CC * 9; i += 256) {
        int cch = i / 9, tap = i - 9 * (i / 9);
        wd4[(((cch >> 2) * 9) + tap) * 4 + (cch & 3)] =
            __ldg(w + (size_t)cch * (CC * 9) + cch * 9 + tap);
    }
    if (tid < CC) {
        cbs[tid] = cb[tid];
        gss[tid] = gscale[tid];
        gbs[tid] = gbias[tid];
    }
    CPA_WAIT0();
    __syncthreads();

    const int lx = tid & 31;
    const int ly = tid >> 5;
    const int center = (ly + 1) * HALO_W + (lx + 1);
    const float* cp = xs + center * K2_PAD;

    // m = max_c center + 1
    float m = -1e30f;
#pragma unroll
    for (int c4 = 0; c4 < 16; c4++) {
        float4 v = *(const float4*)(cp + c4 * 4);
        m = fmaxf(m, fmaxf(fmaxf(v.x, v.y), fmaxf(v.z, v.w)));
    }
    m += 1.0f;

    float s = 0.f;
    for (int g = 0; g < GG; g++) {
        float4 c0 = *(const float4*)(cp + (g * 2 + 0) * 4);
        float4 c1 = *(const float4*)(cp + (g * 2 + 1) * 4);
        float sum = (c0.x + c0.y) + (c0.z + c0.w) + (c1.x + c1.y) + (c1.z + c1.w);
        float mean = sum * (1.0f / GS);
        float vs = 0.f;
        {
            float d;
            d = c0.x - mean; vs = fmaf(d, d, vs);
            d = c0.y - mean; vs = fmaf(d, d, vs);
            d = c0.z - mean; vs = fmaf(d, d, vs);
            d = c0.w - mean; vs = fmaf(d, d, vs);
            d = c1.x - mean; vs = fmaf(d, d, vs);
            d = c1.y - mean; vs = fmaf(d, d, vs);
            d = c1.z - mean; vs = fmaf(d, d, vs);
            d = c1.w - mean; vs = fmaf(d, d, vs);
        }
        float inv = rsqrtf(vs * (1.0f / GS) + 1e-5f);

#pragma unroll
        for (int half = 0; half < 2; half++) {
            int c4 = g * 2 + half;
            float4 acc = *(const float4*)(cbs + c4 * 4);
            const float4* wrow = (const float4*)(wd4 + c4 * 36);
#pragma unroll
            for (int t = 0; t < 9; t++) {
                int dy = t / 3, dx = t - 3 * (t / 3);
                const float4 v = *(const float4*)(xs
                    + ((ly + dy) * HALO_W + (lx + dx)) * K2_PAD + c4 * 4);
                float4 wv = wrow[t];
                acc.x = fmaf(wv.x, v.x, acc.x);
                acc.y = fmaf(wv.y, v.y, acc.y);
                acc.z = fmaf(wv.z, v.z, acc.z);
                acc.w = fmaf(wv.w, v.w, acc.w);
            }
            float4 gsv = *(const float4*)(gss + c4 * 4);
            float4 gbv = *(const float4*)(gbs + c4 * 4);
            float4 ctr = half ? c1 : c0;
#pragma unroll
            for (int k = 0; k < 4; k++) {
                float a  = (k == 0) ? acc.x : (k == 1) ? acc.y : (k == 2) ? acc.z : acc.w;
                float gsc = (k == 0) ? gsv.x : (k == 1) ? gsv.y : (k == 2) ? gsv.z : gsv.w;
                float gbc = (k == 0) ? gbv.x : (k == 1) ? gbv.y : (k == 2) ? gbv.z : gbv.w;
                float ctc = (k == 0) ? ctr.x : (k == 1) ? ctr.y : (k == 2) ? ctr.z : ctr.w;
                float norm = (a - mean) * inv * gsc + gbc;
                float gate = __saturatef(norm * (1.0f / 6.0f) + 0.5f);
                float th;
                asm("tanh.approx.f32 %0, %1;" : "=f"(th) : "f"(norm));
                float v = ctc + th * gate;
                s += __expf(v - m);
            }
        }
    }

    out[((size_t)b << 16) + (h0 + ly) * WW + (w0 + lx)] = m + __logf(s);
}

// ---------------------------------------------------------------------------
extern "C" void kernel_launch(void* const* d_in, const int* in_sizes, int n_in,
                              void* d_out, int out_size)
{
    const float* x   = (const float*)d_in[0];
    const float* w   = (const float*)d_in[1];
    const float* cb  = (const float*)d_in[2];
    const float* gsc = (const float*)d_in[3];
    const float* gbi = (const float*)d_in[4];
    float* out = (float*)d_out;

    cudaFuncSetAttribute(k0_xconv, cudaFuncAttributeMaxDynamicSharedMemorySize, K0X_SMEM);
    cudaFuncSetAttribute(k1_conv,  cudaFuncAttributeMaxDynamicSharedMemorySize, SMEM1);
    cudaFuncSetAttribute(k2_fused, cudaFuncAttributeMaxDynamicSharedMemorySize, K2_SMEM_BYTES);

    k0_wconv<<<9, 256>>>(w);
    k0_xconv<<<BB * HH, 256, K0X_SMEM>>>(x);

    dim3 grid1(2, 128, BB);
    k1_conv<<<grid1, 256, SMEM1>>>(cb);

    dim3 grid2(WW / TW, HH / TH, BB);
    k2_fused<<<grid2, 256, K2_SMEM_BYTES>>>(w, cb, gsc, gbi, out);
}